// round 1
// baseline (speedup 1.0000x reference)
#include <cuda_runtime.h>
#include <math.h>

#define Bc 4
#define Tc 1024
#define Dc 1024
#define Hc 16
#define HSc 64
#define Lc 2047

// -------- scratch (static device globals; no allocations allowed) --------
__device__ float g_q[Bc * Tc * Dc];
__device__ float g_k[Bc * Tc * Dc];
__device__ float g_v[Bc * Tc * Dc];
__device__ float g_p[Lc * Dc];
__device__ float g_ctx[Bc * Tc * Dc];

// ============================================================
// Generic C[M,N] = A[M,K] @ W[N,K]^T + bias   (128x128x8, 8x8/thread)
// ============================================================
__global__ void sgemm_nt(const float* __restrict__ A, const float* __restrict__ W,
                         const float* __restrict__ bias, float* __restrict__ C,
                         int M, int N, int K) {
    __shared__ float As[8][128];
    __shared__ float Ws[8][128];
    int tid = threadIdx.x;
    int m0 = blockIdx.y * 128, n0 = blockIdx.x * 128;
    int lm = tid >> 1;
    int lk = (tid & 1) * 4;
    int tm = (tid >> 4) * 8;
    int tn = (tid & 15) * 8;
    float acc[8][8];
#pragma unroll
    for (int i = 0; i < 8; i++)
#pragma unroll
        for (int j = 0; j < 8; j++) acc[i][j] = 0.f;

    for (int k0 = 0; k0 < K; k0 += 8) {
        float4 av = make_float4(0.f, 0.f, 0.f, 0.f);
        int gm = m0 + lm;
        if (gm < M) av = *(const float4*)(A + (size_t)gm * K + k0 + lk);
        As[lk + 0][lm] = av.x; As[lk + 1][lm] = av.y;
        As[lk + 2][lm] = av.z; As[lk + 3][lm] = av.w;
        float4 wv = *(const float4*)(W + (size_t)(n0 + lm) * K + k0 + lk);
        Ws[lk + 0][lm] = wv.x; Ws[lk + 1][lm] = wv.y;
        Ws[lk + 2][lm] = wv.z; Ws[lk + 3][lm] = wv.w;
        __syncthreads();
#pragma unroll
        for (int kk = 0; kk < 8; kk++) {
            float a[8], b[8];
            *(float4*)(a + 0) = *(const float4*)&As[kk][tm];
            *(float4*)(a + 4) = *(const float4*)&As[kk][tm + 4];
            *(float4*)(b + 0) = *(const float4*)&Ws[kk][tn];
            *(float4*)(b + 4) = *(const float4*)&Ws[kk][tn + 4];
#pragma unroll
            for (int i = 0; i < 8; i++)
#pragma unroll
                for (int j = 0; j < 8; j++)
                    acc[i][j] = fmaf(a[i], b[j], acc[i][j]);
        }
        __syncthreads();
    }

    float bs[8];
#pragma unroll
    for (int j = 0; j < 8; j++) bs[j] = bias ? bias[n0 + tn + j] : 0.f;
#pragma unroll
    for (int i = 0; i < 8; i++) {
        int gm = m0 + tm + i;
        if (gm >= M) continue;
        float4 o0, o1;
        o0.x = acc[i][0] + bs[0]; o0.y = acc[i][1] + bs[1];
        o0.z = acc[i][2] + bs[2]; o0.w = acc[i][3] + bs[3];
        o1.x = acc[i][4] + bs[4]; o1.y = acc[i][5] + bs[5];
        o1.z = acc[i][6] + bs[6]; o1.w = acc[i][7] + bs[7];
        *(float4*)(C + (size_t)gm * N + n0 + tn + 0) = o0;
        *(float4*)(C + (size_t)gm * N + n0 + tn + 4) = o1;
    }
}

// ============================================================
// scores_ac[bh][q][j] = sum_d (q[b,q,h,d]+u[h,d]) * k[b,j,h,d]
// 128x128 tiles over (q,j), K=64.  Writes (initializes) S.
// ============================================================
__global__ void attn_ac(const float* __restrict__ q, const float* __restrict__ k,
                        const float* __restrict__ u, float* __restrict__ S) {
    __shared__ float As[8][128];
    __shared__ float Bs[8][128];
    int tid = threadIdx.x;
    int bh = blockIdx.z;
    int b = bh >> 4, h = bh & 15;
    int q0 = blockIdx.y * 128, j0 = blockIdx.x * 128;
    int lm = tid >> 1;
    int lk = (tid & 1) * 4;
    int tm = (tid >> 4) * 8;
    int tn = (tid & 15) * 8;
    float acc[8][8];
#pragma unroll
    for (int i = 0; i < 8; i++)
#pragma unroll
        for (int j = 0; j < 8; j++) acc[i][j] = 0.f;

    for (int k0 = 0; k0 < HSc; k0 += 8) {
        float4 av = *(const float4*)(q + (((size_t)(b * Tc + q0 + lm)) * Hc + h) * HSc + k0 + lk);
        float4 uv = *(const float4*)(u + h * HSc + k0 + lk);
        av.x += uv.x; av.y += uv.y; av.z += uv.z; av.w += uv.w;
        As[lk + 0][lm] = av.x; As[lk + 1][lm] = av.y;
        As[lk + 2][lm] = av.z; As[lk + 3][lm] = av.w;
        float4 bvv = *(const float4*)(k + (((size_t)(b * Tc + j0 + lm)) * Hc + h) * HSc + k0 + lk);
        Bs[lk + 0][lm] = bvv.x; Bs[lk + 1][lm] = bvv.y;
        Bs[lk + 2][lm] = bvv.z; Bs[lk + 3][lm] = bvv.w;
        __syncthreads();
#pragma unroll
        for (int kk = 0; kk < 8; kk++) {
            float a[8], bb[8];
            *(float4*)(a + 0) = *(const float4*)&As[kk][tm];
            *(float4*)(a + 4) = *(const float4*)&As[kk][tm + 4];
            *(float4*)(bb + 0) = *(const float4*)&Bs[kk][tn];
            *(float4*)(bb + 4) = *(const float4*)&Bs[kk][tn + 4];
#pragma unroll
            for (int i = 0; i < 8; i++)
#pragma unroll
                for (int j = 0; j < 8; j++)
                    acc[i][j] = fmaf(a[i], bb[j], acc[i][j]);
        }
        __syncthreads();
    }

    size_t base = (size_t)bh * Tc * Tc;
#pragma unroll
    for (int i = 0; i < 8; i++) {
        size_t roff = base + (size_t)(q0 + tm + i) * Tc + j0 + tn;
        *(float4*)(S + roff + 0) = make_float4(acc[i][0], acc[i][1], acc[i][2], acc[i][3]);
        *(float4*)(S + roff + 4) = make_float4(acc[i][4], acc[i][5], acc[i][6], acc[i][7]);
    }
}

// ============================================================
// scores_bd:  bd[q, l] = sum_d (q[b,q,h,d]+v[h,d]) * p[l,h,d]
// contributes to S[q][jc] with jc = q + l - (T-1).
// Diagonal band: per q-tile only l in [896-q0, 2046-q0] needed -> 9 tiles.
// ============================================================
__global__ void attn_bd(const float* __restrict__ q, const float* __restrict__ p,
                        const float* __restrict__ v, float* __restrict__ S) {
    __shared__ float As[8][128];
    __shared__ float Bs[8][128];
    int tid = threadIdx.x;
    int bh = blockIdx.z;
    int b = bh >> 4, h = bh & 15;
    int q0 = blockIdx.y * 128;
    int c0 = (Tc - 1) - (q0 + 127) + blockIdx.x * 128;  // first l of this tile (>=0)
    int lm = tid >> 1;
    int lk = (tid & 1) * 4;
    int tm = (tid >> 4) * 8;
    int tn = (tid & 15) * 8;
    float acc[8][8];
#pragma unroll
    for (int i = 0; i < 8; i++)
#pragma unroll
        for (int j = 0; j < 8; j++) acc[i][j] = 0.f;

    for (int k0 = 0; k0 < HSc; k0 += 8) {
        float4 av = *(const float4*)(q + (((size_t)(b * Tc + q0 + lm)) * Hc + h) * HSc + k0 + lk);
        float4 vv = *(const float4*)(v + h * HSc + k0 + lk);
        av.x += vv.x; av.y += vv.y; av.z += vv.z; av.w += vv.w;
        As[lk + 0][lm] = av.x; As[lk + 1][lm] = av.y;
        As[lk + 2][lm] = av.z; As[lk + 3][lm] = av.w;
        int l = c0 + lm;
        float4 bvv = make_float4(0.f, 0.f, 0.f, 0.f);
        if (l >= 0 && l < Lc)
            bvv = *(const float4*)(p + ((size_t)l * Hc + h) * HSc + k0 + lk);
        Bs[lk + 0][lm] = bvv.x; Bs[lk + 1][lm] = bvv.y;
        Bs[lk + 2][lm] = bvv.z; Bs[lk + 3][lm] = bvv.w;
        __syncthreads();
#pragma unroll
        for (int kk = 0; kk < 8; kk++) {
            float a[8], bb[8];
            *(float4*)(a + 0) = *(const float4*)&As[kk][tm];
            *(float4*)(a + 4) = *(const float4*)&As[kk][tm + 4];
            *(float4*)(bb + 0) = *(const float4*)&Bs[kk][tn];
            *(float4*)(bb + 4) = *(const float4*)&Bs[kk][tn + 4];
#pragma unroll
            for (int i = 0; i < 8; i++)
#pragma unroll
                for (int j = 0; j < 8; j++)
                    acc[i][j] = fmaf(a[i], bb[j], acc[i][j]);
        }
        __syncthreads();
    }

    size_t base = (size_t)bh * Tc * Tc;
#pragma unroll
    for (int i = 0; i < 8; i++) {
        int qq = q0 + tm + i;
#pragma unroll
        for (int j = 0; j < 8; j++) {
            int l = c0 + tn + j;
            int jc = qq + l - (Tc - 1);
            if (l >= 0 && l < Lc && jc >= 0 && jc < Tc) {
                size_t idx = base + (size_t)qq * Tc + jc;
                S[idx] += acc[i][j];
            }
        }
    }
}

// ============================================================
// Row softmax in place over T=1024 columns (with 1/sqrt(HS)=0.125 scaling)
// ============================================================
__global__ void softmax_rows(float* __restrict__ S) {
    __shared__ float red[8];
    int tid = threadIdx.x;
    int lane = tid & 31, wid = tid >> 5;
    float* r = S + (size_t)blockIdx.x * Tc;
    float4 x = *(float4*)(r + tid * 4);
    x.x *= 0.125f; x.y *= 0.125f; x.z *= 0.125f; x.w *= 0.125f;

    float m = fmaxf(fmaxf(x.x, x.y), fmaxf(x.z, x.w));
#pragma unroll
    for (int o = 16; o; o >>= 1) m = fmaxf(m, __shfl_xor_sync(0xffffffffu, m, o));
    if (lane == 0) red[wid] = m;
    __syncthreads();
    if (tid < 32) {
        float t = (tid < 8) ? red[tid] : -3.4e38f;
#pragma unroll
        for (int o = 4; o; o >>= 1) t = fmaxf(t, __shfl_xor_sync(0xffffffffu, t, o));
        if (tid == 0) red[0] = t;
    }
    __syncthreads();
    float gm = red[0];
    __syncthreads();

    float4 e;
    e.x = expf(x.x - gm); e.y = expf(x.y - gm);
    e.z = expf(x.z - gm); e.w = expf(x.w - gm);
    float s = e.x + e.y + e.z + e.w;
#pragma unroll
    for (int o = 16; o; o >>= 1) s += __shfl_xor_sync(0xffffffffu, s, o);
    if (lane == 0) red[wid] = s;
    __syncthreads();
    if (tid < 32) {
        float t = (tid < 8) ? red[tid] : 0.f;
#pragma unroll
        for (int o = 4; o; o >>= 1) t += __shfl_xor_sync(0xffffffffu, t, o);
        if (tid == 0) red[0] = t;
    }
    __syncthreads();
    float inv = 1.f / red[0];
    e.x *= inv; e.y *= inv; e.z *= inv; e.w *= inv;
    *(float4*)(r + tid * 4) = e;
}

// ============================================================
// ctx[b,q,h,:] = sum_k probs[bh,q,k] * v[b,k,h,:]   (256x64x16 tiles, 8x8/thr)
// ============================================================
__global__ void attn_ctx(const float* __restrict__ P, const float* __restrict__ V,
                         float* __restrict__ ctx) {
    __shared__ float As[16][260];
    __shared__ float Bs[16][68];
    int tid = threadIdx.x;
    int bh = blockIdx.z;
    int b = bh >> 4, h = bh & 15;
    int q0 = blockIdx.y * 256;
    int arow = tid >> 2, akq = (tid & 3) * 4;
    int bkk = tid >> 4, bnq = (tid & 15) * 4;
    int tm = (tid >> 3) * 8, tn = (tid & 7) * 8;
    float acc[8][8];
#pragma unroll
    for (int i = 0; i < 8; i++)
#pragma unroll
        for (int j = 0; j < 8; j++) acc[i][j] = 0.f;

    size_t Pbase = (size_t)bh * Tc * Tc;
    for (int k0 = 0; k0 < Tc; k0 += 16) {
#pragma unroll
        for (int rr = 0; rr < 4; rr++) {
            int row = arow + rr * 64;
            float4 av = *(const float4*)(P + Pbase + (size_t)(q0 + row) * Tc + k0 + akq);
            As[akq + 0][row] = av.x; As[akq + 1][row] = av.y;
            As[akq + 2][row] = av.z; As[akq + 3][row] = av.w;
        }
        float4 bvv = *(const float4*)(V + (((size_t)(b * Tc + k0 + bkk)) * Hc + h) * HSc + bnq);
        *(float4*)&Bs[bkk][bnq] = bvv;
        __syncthreads();
#pragma unroll
        for (int kk = 0; kk < 16; kk++) {
            float a[8], bb[8];
            *(float4*)(a + 0) = *(const float4*)&As[kk][tm];
            *(float4*)(a + 4) = *(const float4*)&As[kk][tm + 4];
            *(float4*)(bb + 0) = *(const float4*)&Bs[kk][tn];
            *(float4*)(bb + 4) = *(const float4*)&Bs[kk][tn + 4];
#pragma unroll
            for (int i = 0; i < 8; i++)
#pragma unroll
                for (int j = 0; j < 8; j++)
                    acc[i][j] = fmaf(a[i], bb[j], acc[i][j]);
        }
        __syncthreads();
    }

#pragma unroll
    for (int i = 0; i < 8; i++) {
        size_t off = (((size_t)(b * Tc + q0 + tm + i)) * Hc + h) * HSc + tn;
        *(float4*)(ctx + off + 0) = make_float4(acc[i][0], acc[i][1], acc[i][2], acc[i][3]);
        *(float4*)(ctx + off + 4) = make_float4(acc[i][4], acc[i][5], acc[i][6], acc[i][7]);
    }
}

// ============================================================
extern "C" void kernel_launch(void* const* d_in, const int* in_sizes, int n_in,
                              void* d_out, int out_size) {
    const float* hs  = (const float*)d_in[0];
    const float* rpe = (const float*)d_in[1];
    const float* Wq  = (const float*)d_in[2];
    const float* bq  = (const float*)d_in[3];
    const float* Wk  = (const float*)d_in[4];
    const float* bk  = (const float*)d_in[5];
    const float* Wv  = (const float*)d_in[6];
    const float* bv  = (const float*)d_in[7];
    const float* Wo  = (const float*)d_in[8];
    const float* bo  = (const float*)d_in[9];
    const float* Wp  = (const float*)d_in[10];
    const float* pu  = (const float*)d_in[11];
    const float* pvb = (const float*)d_in[12];

    float* out = (float*)d_out;                 // (B,T,D)
    float* S   = out + (size_t)Bc * Tc * Dc;    // (B,H,T,T) probs region (used as score scratch)

    float *pq, *pk, *pv, *pp, *pctx;
    cudaGetSymbolAddress((void**)&pq,   g_q);
    cudaGetSymbolAddress((void**)&pk,   g_k);
    cudaGetSymbolAddress((void**)&pv,   g_v);
    cudaGetSymbolAddress((void**)&pp,   g_p);
    cudaGetSymbolAddress((void**)&pctx, g_ctx);

    dim3 thr(256);
    // projections
    sgemm_nt<<<dim3(8, 32), thr>>>(hs,  Wq, bq, pq, Bc * Tc, Dc, Dc);
    sgemm_nt<<<dim3(8, 32), thr>>>(hs,  Wk, bk, pk, Bc * Tc, Dc, Dc);
    sgemm_nt<<<dim3(8, 32), thr>>>(hs,  Wv, bv, pv, Bc * Tc, Dc, Dc);
    sgemm_nt<<<dim3(8, 16), thr>>>(rpe, Wp, nullptr, pp, Lc, Dc, Dc);
    // attention scores
    attn_ac<<<dim3(8, 8, Bc * Hc), thr>>>(pq, pk, pu, S);
    attn_bd<<<dim3(9, 8, Bc * Hc), thr>>>(pq, pp, pvb, S);
    // softmax -> probs (in place, also the 2nd output)
    softmax_rows<<<Bc * Hc * Tc, thr>>>(S);
    // context + output projection
    attn_ctx<<<dim3(1, 4, Bc * Hc), thr>>>(S, pv, pctx);
    sgemm_nt<<<dim3(8, 32), thr>>>(pctx, Wo, bo, out, Bc * Tc, Dc, Dc);
}

// round 2
// speedup vs baseline: 1.0111x; 1.0111x over previous
#include <cuda_runtime.h>
#include <math.h>
#include <stdint.h>

#define Bc 4
#define Tc 1024
#define Dc 1024
#define Hc 16
#define HSc 64
#define Lc 2047

// -------- scratch (static device globals; no allocations allowed) --------
__device__ float g_q[Bc * Tc * Dc];
__device__ float g_k[Bc * Tc * Dc];
__device__ float g_v[Bc * Tc * Dc];
__device__ float g_p[Lc * Dc];
__device__ float g_ctx[Bc * Tc * Dc];

// ============================================================
// tf32 helpers (tf32x3 split: x = hi + lo, drop lo*lo term)
// ============================================================
__device__ __forceinline__ uint32_t tf32_of(float x) {
    uint32_t r;
    asm("cvt.rna.tf32.f32 %0, %1;" : "=r"(r) : "f"(x));
    return r;
}
__device__ __forceinline__ void split_tf32(float x, uint32_t& hi, uint32_t& lo) {
    hi = tf32_of(x);
    lo = tf32_of(x - __uint_as_float(hi));
}
__device__ __forceinline__ void mma8(float* d, const uint32_t* a, const uint32_t* b) {
    asm volatile(
        "mma.sync.aligned.m16n8k8.row.col.f32.tf32.tf32.f32 "
        "{%0,%1,%2,%3},{%4,%5,%6,%7},{%8,%9},{%0,%1,%2,%3};"
        : "+f"(d[0]), "+f"(d[1]), "+f"(d[2]), "+f"(d[3])
        : "r"(a[0]), "r"(a[1]), "r"(a[2]), "r"(a[3]), "r"(b[0]), "r"(b[1]));
}

// Compute one K=16 slab from smem tiles.
// As layout: [16][136] (k-major, m inner). Bs layout: [16][BSTR] (k-major, n inner).
template <int TM, int TN, int BSTR>
__device__ __forceinline__ void compute_k16(const float* __restrict__ As,
                                            const float* __restrict__ Bs,
                                            float acc[TM][TN][4],
                                            int mBase, int nBase, int gid, int tig) {
#pragma unroll
    for (int k8 = 0; k8 < 16; k8 += 8) {
        uint32_t ahi[TM][4], alo[TM][4];
#pragma unroll
        for (int mt = 0; mt < TM; mt++) {
            int r0 = mBase + mt * 16 + gid;
            const float* a0 = As + (k8 + tig) * 136;
            const float* a4 = As + (k8 + tig + 4) * 136;
            split_tf32(a0[r0],     ahi[mt][0], alo[mt][0]);
            split_tf32(a0[r0 + 8], ahi[mt][1], alo[mt][1]);
            split_tf32(a4[r0],     ahi[mt][2], alo[mt][2]);
            split_tf32(a4[r0 + 8], ahi[mt][3], alo[mt][3]);
        }
        uint32_t bhi[TN][2], blo[TN][2];
#pragma unroll
        for (int nt = 0; nt < TN; nt++) {
            int c = nBase + nt * 8 + gid;
            split_tf32(Bs[(k8 + tig) * BSTR + c],     bhi[nt][0], blo[nt][0]);
            split_tf32(Bs[(k8 + 4 + tig) * BSTR + c], bhi[nt][1], blo[nt][1]);
        }
#pragma unroll
        for (int mt = 0; mt < TM; mt++)
#pragma unroll
            for (int nt = 0; nt < TN; nt++) {
                mma8(acc[mt][nt], ahi[mt], bhi[nt]);
                mma8(acc[mt][nt], ahi[mt], blo[nt]);
                mma8(acc[mt][nt], alo[mt], bhi[nt]);
            }
    }
}

// ============================================================
// C[M,N] = A[M,K] @ W[N,K]^T (+bias).  128x128 block, BK=16, 256 thr.
// ============================================================
__global__ __launch_bounds__(256, 1) void gemm_tc_nt(
    const float* __restrict__ A, const float* __restrict__ W,
    const float* __restrict__ bias, float* __restrict__ C,
    int M, int N, int K) {
    __shared__ float As[2][16][136];
    __shared__ float Bs[2][16][136];
    const int tid = threadIdx.x;
    const int m0 = blockIdx.y * 128, n0 = blockIdx.x * 128;
    const int lrow = tid >> 1, lk = (tid & 1) * 8;
    const int lane = tid & 31, wid = tid >> 5;
    const int mBase = (wid >> 1) * 32, nBase = (wid & 1) * 64;
    const int gid = lane >> 2, tig = lane & 3;

    float acc[2][8][4];
#pragma unroll
    for (int i = 0; i < 2; i++)
#pragma unroll
        for (int j = 0; j < 8; j++)
#pragma unroll
            for (int c = 0; c < 4; c++) acc[i][j][c] = 0.f;

    const bool aval = (m0 + lrow) < M;
    const bool wval = (n0 + lrow) < N;
    const float* Arow = A + (size_t)(m0 + lrow) * K + lk;
    const float* Wrow = W + (size_t)(n0 + lrow) * K + lk;
    const float4 f4z = make_float4(0.f, 0.f, 0.f, 0.f);

    float4 sa0, sa1, sb0, sb1;
    sa0 = aval ? *(const float4*)(Arow + 0) : f4z;
    sa1 = aval ? *(const float4*)(Arow + 4) : f4z;
    sb0 = wval ? *(const float4*)(Wrow + 0) : f4z;
    sb1 = wval ? *(const float4*)(Wrow + 4) : f4z;
    {
        float* as = &As[0][lk][lrow];
        as[0 * 136] = sa0.x; as[1 * 136] = sa0.y; as[2 * 136] = sa0.z; as[3 * 136] = sa0.w;
        as[4 * 136] = sa1.x; as[5 * 136] = sa1.y; as[6 * 136] = sa1.z; as[7 * 136] = sa1.w;
        float* bs = &Bs[0][lk][lrow];
        bs[0 * 136] = sb0.x; bs[1 * 136] = sb0.y; bs[2 * 136] = sb0.z; bs[3 * 136] = sb0.w;
        bs[4 * 136] = sb1.x; bs[5 * 136] = sb1.y; bs[6 * 136] = sb1.z; bs[7 * 136] = sb1.w;
    }
    __syncthreads();

    const int nk = K / 16;
    for (int kt = 0; kt < nk; kt++) {
        const int cur = kt & 1;
        const bool more = (kt + 1) < nk;
        if (more) {
            const float* ap = Arow + (kt + 1) * 16;
            const float* wp = Wrow + (kt + 1) * 16;
            sa0 = aval ? *(const float4*)(ap + 0) : f4z;
            sa1 = aval ? *(const float4*)(ap + 4) : f4z;
            sb0 = wval ? *(const float4*)(wp + 0) : f4z;
            sb1 = wval ? *(const float4*)(wp + 4) : f4z;
        }
        compute_k16<2, 8, 136>(&As[cur][0][0], &Bs[cur][0][0], acc, mBase, nBase, gid, tig);
        if (more) {
            const int nb = cur ^ 1;
            float* as = &As[nb][lk][lrow];
            as[0 * 136] = sa0.x; as[1 * 136] = sa0.y; as[2 * 136] = sa0.z; as[3 * 136] = sa0.w;
            as[4 * 136] = sa1.x; as[5 * 136] = sa1.y; as[6 * 136] = sa1.z; as[7 * 136] = sa1.w;
            float* bs = &Bs[nb][lk][lrow];
            bs[0 * 136] = sb0.x; bs[1 * 136] = sb0.y; bs[2 * 136] = sb0.z; bs[3 * 136] = sb0.w;
            bs[4 * 136] = sb1.x; bs[5 * 136] = sb1.y; bs[6 * 136] = sb1.z; bs[7 * 136] = sb1.w;
            __syncthreads();
        }
    }

#pragma unroll
    for (int mt = 0; mt < 2; mt++) {
        int r = m0 + mBase + mt * 16 + gid;
#pragma unroll
        for (int nt = 0; nt < 8; nt++) {
            int c = n0 + nBase + nt * 8 + 2 * tig;
            float b0v = bias ? bias[c] : 0.f;
            float b1v = bias ? bias[c + 1] : 0.f;
            if (r < M) {
                float2 o = make_float2(acc[mt][nt][0] + b0v, acc[mt][nt][1] + b1v);
                *(float2*)(C + (size_t)r * N + c) = o;
            }
            if (r + 8 < M) {
                float2 o = make_float2(acc[mt][nt][2] + b0v, acc[mt][nt][3] + b1v);
                *(float2*)(C + (size_t)(r + 8) * N + c) = o;
            }
        }
    }
}

// ============================================================
// scores_ac[bh][q][j] = sum_d (q+u)[b,q,h,d] * k[b,j,h,d]
// ============================================================
__global__ __launch_bounds__(256, 1) void attn_ac_tc(
    const float* __restrict__ q, const float* __restrict__ kk,
    const float* __restrict__ u, float* __restrict__ S) {
    __shared__ float As[2][16][136];
    __shared__ float Bs[2][16][136];
    const int tid = threadIdx.x;
    const int z = blockIdx.z, zb = z >> 4, h = z & 15;
    const int m0 = blockIdx.y * 128, n0 = blockIdx.x * 128;
    const int lrow = tid >> 1, lk = (tid & 1) * 8;
    const int lane = tid & 31, wid = tid >> 5;
    const int mBase = (wid >> 1) * 32, nBase = (wid & 1) * 64;
    const int gid = lane >> 2, tig = lane & 3;

    float acc[2][8][4];
#pragma unroll
    for (int i = 0; i < 2; i++)
#pragma unroll
        for (int j = 0; j < 8; j++)
#pragma unroll
            for (int c = 0; c < 4; c++) acc[i][j][c] = 0.f;

    const float* Arow = q + ((size_t)(zb * Tc) + m0 + lrow) * Dc + h * HSc + lk;
    const float* Brow = kk + ((size_t)(zb * Tc) + n0 + lrow) * Dc + h * HSc + lk;
    const float* uu = u + h * HSc + lk;

    float4 sa0, sa1, sb0, sb1;
    {
        float4 u0 = *(const float4*)(uu + 0), u1 = *(const float4*)(uu + 4);
        sa0 = *(const float4*)(Arow + 0); sa1 = *(const float4*)(Arow + 4);
        sa0.x += u0.x; sa0.y += u0.y; sa0.z += u0.z; sa0.w += u0.w;
        sa1.x += u1.x; sa1.y += u1.y; sa1.z += u1.z; sa1.w += u1.w;
        sb0 = *(const float4*)(Brow + 0); sb1 = *(const float4*)(Brow + 4);
        float* as = &As[0][lk][lrow];
        as[0 * 136] = sa0.x; as[1 * 136] = sa0.y; as[2 * 136] = sa0.z; as[3 * 136] = sa0.w;
        as[4 * 136] = sa1.x; as[5 * 136] = sa1.y; as[6 * 136] = sa1.z; as[7 * 136] = sa1.w;
        float* bs = &Bs[0][lk][lrow];
        bs[0 * 136] = sb0.x; bs[1 * 136] = sb0.y; bs[2 * 136] = sb0.z; bs[3 * 136] = sb0.w;
        bs[4 * 136] = sb1.x; bs[5 * 136] = sb1.y; bs[6 * 136] = sb1.z; bs[7 * 136] = sb1.w;
    }
    __syncthreads();

    const int nk = HSc / 16;  // 4
    for (int kt = 0; kt < nk; kt++) {
        const int cur = kt & 1;
        const bool more = (kt + 1) < nk;
        if (more) {
            int ko = (kt + 1) * 16;
            float4 u0 = *(const float4*)(uu + ko + 0), u1 = *(const float4*)(uu + ko + 4);
            sa0 = *(const float4*)(Arow + ko + 0); sa1 = *(const float4*)(Arow + ko + 4);
            sa0.x += u0.x; sa0.y += u0.y; sa0.z += u0.z; sa0.w += u0.w;
            sa1.x += u1.x; sa1.y += u1.y; sa1.z += u1.z; sa1.w += u1.w;
            sb0 = *(const float4*)(Brow + ko + 0); sb1 = *(const float4*)(Brow + ko + 4);
        }
        compute_k16<2, 8, 136>(&As[cur][0][0], &Bs[cur][0][0], acc, mBase, nBase, gid, tig);
        if (more) {
            const int nb = cur ^ 1;
            float* as = &As[nb][lk][lrow];
            as[0 * 136] = sa0.x; as[1 * 136] = sa0.y; as[2 * 136] = sa0.z; as[3 * 136] = sa0.w;
            as[4 * 136] = sa1.x; as[5 * 136] = sa1.y; as[6 * 136] = sa1.z; as[7 * 136] = sa1.w;
            float* bs = &Bs[nb][lk][lrow];
            bs[0 * 136] = sb0.x; bs[1 * 136] = sb0.y; bs[2 * 136] = sb0.z; bs[3 * 136] = sb0.w;
            bs[4 * 136] = sb1.x; bs[5 * 136] = sb1.y; bs[6 * 136] = sb1.z; bs[7 * 136] = sb1.w;
            __syncthreads();
        }
    }

    size_t base = (size_t)z << 20;
#pragma unroll
    for (int mt = 0; mt < 2; mt++) {
        int r = m0 + mBase + mt * 16 + gid;
#pragma unroll
        for (int nt = 0; nt < 8; nt++) {
            int c = n0 + nBase + nt * 8 + 2 * tig;
            *(float2*)(S + base + (size_t)r * Tc + c) =
                make_float2(acc[mt][nt][0], acc[mt][nt][1]);
            *(float2*)(S + base + (size_t)(r + 8) * Tc + c) =
                make_float2(acc[mt][nt][2], acc[mt][nt][3]);
        }
    }
}

// ============================================================
// scores_bd band:  bd[q,l] = sum_d (q+v)[b,q,h,d] * p[l,h,d]
// scatter-add into S[q][q+l-(T-1)]
// ============================================================
__global__ __launch_bounds__(256, 1) void attn_bd_tc(
    const float* __restrict__ q, const float* __restrict__ p,
    const float* __restrict__ v, float* __restrict__ S) {
    __shared__ float As[2][16][136];
    __shared__ float Bs[2][16][136];
    const int tid = threadIdx.x;
    const int z = blockIdx.z, zb = z >> 4, h = z & 15;
    const int m0 = blockIdx.y * 128;
    const int c0 = (Tc - 1) - (m0 + 127) + blockIdx.x * 128;  // >= 0
    const int lrow = tid >> 1, lk = (tid & 1) * 8;
    const int lane = tid & 31, wid = tid >> 5;
    const int mBase = (wid >> 1) * 32, nBase = (wid & 1) * 64;
    const int gid = lane >> 2, tig = lane & 3;

    float acc[2][8][4];
#pragma unroll
    for (int i = 0; i < 2; i++)
#pragma unroll
        for (int j = 0; j < 8; j++)
#pragma unroll
            for (int c = 0; c < 4; c++) acc[i][j][c] = 0.f;

    const float* Arow = q + ((size_t)(zb * Tc) + m0 + lrow) * Dc + h * HSc + lk;
    const int lidx = c0 + lrow;
    const bool bval = lidx < Lc;
    const float* Brow = p + (size_t)lidx * Dc + h * HSc + lk;
    const float* vv = v + h * HSc + lk;
    const float4 f4z = make_float4(0.f, 0.f, 0.f, 0.f);

    float4 sa0, sa1, sb0, sb1;
    {
        float4 u0 = *(const float4*)(vv + 0), u1 = *(const float4*)(vv + 4);
        sa0 = *(const float4*)(Arow + 0); sa1 = *(const float4*)(Arow + 4);
        sa0.x += u0.x; sa0.y += u0.y; sa0.z += u0.z; sa0.w += u0.w;
        sa1.x += u1.x; sa1.y += u1.y; sa1.z += u1.z; sa1.w += u1.w;
        sb0 = bval ? *(const float4*)(Brow + 0) : f4z;
        sb1 = bval ? *(const float4*)(Brow + 4) : f4z;
        float* as = &As[0][lk][lrow];
        as[0 * 136] = sa0.x; as[1 * 136] = sa0.y; as[2 * 136] = sa0.z; as[3 * 136] = sa0.w;
        as[4 * 136] = sa1.x; as[5 * 136] = sa1.y; as[6 * 136] = sa1.z; as[7 * 136] = sa1.w;
        float* bs = &Bs[0][lk][lrow];
        bs[0 * 136] = sb0.x; bs[1 * 136] = sb0.y; bs[2 * 136] = sb0.z; bs[3 * 136] = sb0.w;
        bs[4 * 136] = sb1.x; bs[5 * 136] = sb1.y; bs[6 * 136] = sb1.z; bs[7 * 136] = sb1.w;
    }
    __syncthreads();

    const int nk = HSc / 16;
    for (int kt = 0; kt < nk; kt++) {
        const int cur = kt & 1;
        const bool more = (kt + 1) < nk;
        if (more) {
            int ko = (kt + 1) * 16;
            float4 u0 = *(const float4*)(vv + ko + 0), u1 = *(const float4*)(vv + ko + 4);
            sa0 = *(const float4*)(Arow + ko + 0); sa1 = *(const float4*)(Arow + ko + 4);
            sa0.x += u0.x; sa0.y += u0.y; sa0.z += u0.z; sa0.w += u0.w;
            sa1.x += u1.x; sa1.y += u1.y; sa1.z += u1.z; sa1.w += u1.w;
            sb0 = bval ? *(const float4*)(Brow + ko + 0) : f4z;
            sb1 = bval ? *(const float4*)(Brow + ko + 4) : f4z;
        }
        compute_k16<2, 8, 136>(&As[cur][0][0], &Bs[cur][0][0], acc, mBase, nBase, gid, tig);
        if (more) {
            const int nb = cur ^ 1;
            float* as = &As[nb][lk][lrow];
            as[0 * 136] = sa0.x; as[1 * 136] = sa0.y; as[2 * 136] = sa0.z; as[3 * 136] = sa0.w;
            as[4 * 136] = sa1.x; as[5 * 136] = sa1.y; as[6 * 136] = sa1.z; as[7 * 136] = sa1.w;
            float* bs = &Bs[nb][lk][lrow];
            bs[0 * 136] = sb0.x; bs[1 * 136] = sb0.y; bs[2 * 136] = sb0.z; bs[3 * 136] = sb0.w;
            bs[4 * 136] = sb1.x; bs[5 * 136] = sb1.y; bs[6 * 136] = sb1.z; bs[7 * 136] = sb1.w;
            __syncthreads();
        }
    }

    size_t base = (size_t)z << 20;
#pragma unroll
    for (int mt = 0; mt < 2; mt++) {
        int qq = m0 + mBase + mt * 16 + gid;
#pragma unroll
        for (int nt = 0; nt < 8; nt++) {
            int lc = c0 + nBase + nt * 8 + 2 * tig;
            int j0 = qq + lc - (Tc - 1);
            if (lc < Lc && j0 >= 0 && j0 < Tc)
                S[base + (size_t)qq * Tc + j0] += acc[mt][nt][0];
            if (lc + 1 < Lc && j0 + 1 >= 0 && j0 + 1 < Tc)
                S[base + (size_t)qq * Tc + j0 + 1] += acc[mt][nt][1];
            int q2 = qq + 8;
            int j2 = q2 + lc - (Tc - 1);
            if (lc < Lc && j2 >= 0 && j2 < Tc)
                S[base + (size_t)q2 * Tc + j2] += acc[mt][nt][2];
            if (lc + 1 < Lc && j2 + 1 >= 0 && j2 + 1 < Tc)
                S[base + (size_t)q2 * Tc + j2 + 1] += acc[mt][nt][3];
        }
    }
}

// ============================================================
// ctx = probs @ V    (128x64 block, BK=16)
// ============================================================
__global__ __launch_bounds__(256, 1) void attn_ctx_tc(
    const float* __restrict__ P, const float* __restrict__ V,
    float* __restrict__ ctx) {
    __shared__ float As[2][16][136];
    __shared__ float Bs[2][16][72];
    const int tid = threadIdx.x;
    const int z = blockIdx.z, zb = z >> 4, h = z & 15;
    const int m0 = blockIdx.y * 128;
    const int lrow = tid >> 1, lk = (tid & 1) * 8;
    const int bk = tid >> 4, bn = (tid & 15) * 4;
    const int lane = tid & 31, wid = tid >> 5;
    const int mBase = wid * 16;
    const int gid = lane >> 2, tig = lane & 3;

    float acc[1][8][4];
#pragma unroll
    for (int j = 0; j < 8; j++)
#pragma unroll
        for (int c = 0; c < 4; c++) acc[0][j][c] = 0.f;

    const float* Arow = P + ((size_t)z << 20) + (size_t)(m0 + lrow) * Tc + lk;
    const float* Brow = V + ((size_t)(zb * Tc) + bk) * Dc + h * HSc + bn;

    float4 sa0, sa1, sb0;
    {
        sa0 = *(const float4*)(Arow + 0); sa1 = *(const float4*)(Arow + 4);
        sb0 = *(const float4*)(Brow);
        float* as = &As[0][lk][lrow];
        as[0 * 136] = sa0.x; as[1 * 136] = sa0.y; as[2 * 136] = sa0.z; as[3 * 136] = sa0.w;
        as[4 * 136] = sa1.x; as[5 * 136] = sa1.y; as[6 * 136] = sa1.z; as[7 * 136] = sa1.w;
        *(float4*)(&Bs[0][bk][bn]) = sb0;
    }
    __syncthreads();

    const int nk = Tc / 16;  // 64
    for (int kt = 0; kt < nk; kt++) {
        const int cur = kt & 1;
        const bool more = (kt + 1) < nk;
        if (more) {
            sa0 = *(const float4*)(Arow + (kt + 1) * 16 + 0);
            sa1 = *(const float4*)(Arow + (kt + 1) * 16 + 4);
            sb0 = *(const float4*)(Brow + (size_t)(kt + 1) * 16 * Dc);
        }
        compute_k16<1, 8, 72>(&As[cur][0][0], &Bs[cur][0][0], acc, mBase, 0, gid, tig);
        if (more) {
            const int nb = cur ^ 1;
            float* as = &As[nb][lk][lrow];
            as[0 * 136] = sa0.x; as[1 * 136] = sa0.y; as[2 * 136] = sa0.z; as[3 * 136] = sa0.w;
            as[4 * 136] = sa1.x; as[5 * 136] = sa1.y; as[6 * 136] = sa1.z; as[7 * 136] = sa1.w;
            *(float4*)(&Bs[nb][bk][bn]) = sb0;
            __syncthreads();
        }
    }

    int r = m0 + mBase + gid;
#pragma unroll
    for (int nt = 0; nt < 8; nt++) {
        int c = nt * 8 + 2 * tig;
        float* d0 = ctx + ((size_t)(zb * Tc) + r) * Dc + h * HSc + c;
        *(float2*)d0 = make_float2(acc[0][nt][0], acc[0][nt][1]);
        float* d1 = ctx + ((size_t)(zb * Tc) + r + 8) * Dc + h * HSc + c;
        *(float2*)d1 = make_float2(acc[0][nt][2], acc[0][nt][3]);
    }
}

// ============================================================
// Row softmax in place over T=1024 columns (with 1/sqrt(HS)=0.125 scaling)
// ============================================================
__global__ void softmax_rows(float* __restrict__ S) {
    __shared__ float red[8];
    int tid = threadIdx.x;
    int lane = tid & 31, wid = tid >> 5;
    float* r = S + (size_t)blockIdx.x * Tc;
    float4 x = *(float4*)(r + tid * 4);
    x.x *= 0.125f; x.y *= 0.125f; x.z *= 0.125f; x.w *= 0.125f;

    float m = fmaxf(fmaxf(x.x, x.y), fmaxf(x.z, x.w));
#pragma unroll
    for (int o = 16; o; o >>= 1) m = fmaxf(m, __shfl_xor_sync(0xffffffffu, m, o));
    if (lane == 0) red[wid] = m;
    __syncthreads();
    if (tid < 32) {
        float t = (tid < 8) ? red[tid] : -3.4e38f;
#pragma unroll
        for (int o = 4; o; o >>= 1) t = fmaxf(t, __shfl_xor_sync(0xffffffffu, t, o));
        if (tid == 0) red[0] = t;
    }
    __syncthreads();
    float gm = red[0];
    __syncthreads();

    float4 e;
    e.x = expf(x.x - gm); e.y = expf(x.y - gm);
    e.z = expf(x.z - gm); e.w = expf(x.w - gm);
    float s = e.x + e.y + e.z + e.w;
#pragma unroll
    for (int o = 16; o; o >>= 1) s += __shfl_xor_sync(0xffffffffu, s, o);
    if (lane == 0) red[wid] = s;
    __syncthreads();
    if (tid < 32) {
        float t = (tid < 8) ? red[tid] : 0.f;
#pragma unroll
        for (int o = 4; o; o >>= 1) t += __shfl_xor_sync(0xffffffffu, t, o);
        if (tid == 0) red[0] = t;
    }
    __syncthreads();
    float inv = 1.f / red[0];
    e.x *= inv; e.y *= inv; e.z *= inv; e.w *= inv;
    *(float4*)(r + tid * 4) = e;
}

// ============================================================
extern "C" void kernel_launch(void* const* d_in, const int* in_sizes, int n_in,
                              void* d_out, int out_size) {
    const float* hs  = (const float*)d_in[0];
    const float* rpe = (const float*)d_in[1];
    const float* Wq  = (const float*)d_in[2];
    const float* bq  = (const float*)d_in[3];
    const float* Wk  = (const float*)d_in[4];
    const float* bk  = (const float*)d_in[5];
    const float* Wv  = (const float*)d_in[6];
    const float* bv  = (const float*)d_in[7];
    const float* Wo  = (const float*)d_in[8];
    const float* bo  = (const float*)d_in[9];
    const float* Wp  = (const float*)d_in[10];
    const float* pu  = (const float*)d_in[11];
    const float* pvb = (const float*)d_in[12];

    float* out = (float*)d_out;                 // (B,T,D)
    float* S   = out + (size_t)Bc * Tc * Dc;    // (B,H,T,T) probs

    float *pq, *pk, *pv, *pp, *pctx;
    cudaGetSymbolAddress((void**)&pq,   g_q);
    cudaGetSymbolAddress((void**)&pk,   g_k);
    cudaGetSymbolAddress((void**)&pv,   g_v);
    cudaGetSymbolAddress((void**)&pp,   g_p);
    cudaGetSymbolAddress((void**)&pctx, g_ctx);

    dim3 thr(256);
    gemm_tc_nt<<<dim3(8, 32), thr>>>(hs,  Wq, bq, pq, Bc * Tc, Dc, Dc);
    gemm_tc_nt<<<dim3(8, 32), thr>>>(hs,  Wk, bk, pk, Bc * Tc, Dc, Dc);
    gemm_tc_nt<<<dim3(8, 32), thr>>>(hs,  Wv, bv, pv, Bc * Tc, Dc, Dc);
    gemm_tc_nt<<<dim3(8, 16), thr>>>(rpe, Wp, nullptr, pp, Lc, Dc, Dc);

    attn_ac_tc<<<dim3(8, 8, Bc * Hc), thr>>>(pq, pk, pu, S);
    attn_bd_tc<<<dim3(9, 8, Bc * Hc), thr>>>(pq, pp, pvb, S);

    softmax_rows<<<Bc * Hc * Tc, thr>>>(S);

    attn_ctx_tc<<<dim3(1, 8, Bc * Hc), thr>>>(S, pv, pctx);
    gemm_tc_nt<<<dim3(8, 32), thr>>>(pctx, Wo, bo, out, Bc * Tc, Dc, Dc);
}

// round 3
// speedup vs baseline: 1.0622x; 1.0505x over previous
#include <cuda_runtime.h>
#include <math.h>
#include <stdint.h>

#define Bc 4
#define Tc 1024
#define Dc 1024
#define Hc 16
#define HSc 64
#define Lc 2047

// -------- scratch (static device globals; no allocations allowed) --------
__device__ float g_q[Bc * Tc * Dc];
__device__ float g_k[Bc * Tc * Dc];
__device__ float g_v[Bc * Tc * Dc];
__device__ float g_p[Lc * Dc];
__device__ float g_ctx[Bc * Tc * Dc];

// ============================================================
// tf32 helpers (tf32x3 split: x = hi + lo, drop lo*lo term)
// ============================================================
__device__ __forceinline__ uint32_t tf32_of(float x) {
    uint32_t r;
    asm("cvt.rna.tf32.f32 %0, %1;" : "=r"(r) : "f"(x));
    return r;
}
__device__ __forceinline__ void split_tf32(float x, uint32_t& hi, uint32_t& lo) {
    hi = tf32_of(x);
    lo = tf32_of(x - __uint_as_float(hi));
}
__device__ __forceinline__ void mma8(float* d, const uint32_t* a, const uint32_t* b) {
    asm volatile(
        "mma.sync.aligned.m16n8k8.row.col.f32.tf32.tf32.f32 "
        "{%0,%1,%2,%3},{%4,%5,%6,%7},{%8,%9},{%0,%1,%2,%3};"
        : "+f"(d[0]), "+f"(d[1]), "+f"(d[2]), "+f"(d[3])
        : "r"(a[0]), "r"(a[1]), "r"(a[2]), "r"(a[3]), "r"(b[0]), "r"(b[1]));
}
__device__ __forceinline__ void mma_grp(float* acc, const uint32_t ah[4], const uint32_t al[4],
                                        float b0f, float b1f) {
    uint32_t bh[2], bl[2];
    split_tf32(b0f, bh[0], bl[0]);
    split_tf32(b1f, bh[1], bl[1]);
    mma8(acc, ah, bh);
    mma8(acc, ah, bl);
    mma8(acc, al, bh);
}

// ============================================================
// Fused QKV projection: C{q,k,v}[4096,1024] = hs @ W{q,k,v}^T + b
// 128x128 block, BK=16, double buffered. grid (24, 32).
// ============================================================
__global__ __launch_bounds__(256, 1) void gemm_qkv(
    const float* __restrict__ A,
    const float* __restrict__ Wq, const float* __restrict__ Wk, const float* __restrict__ Wv,
    const float* __restrict__ bq, const float* __restrict__ bk, const float* __restrict__ bv,
    float* __restrict__ Cq, float* __restrict__ Ck, float* __restrict__ Cv) {
    __shared__ float As[2][16][136];
    __shared__ float Bs[2][16][136];
    const int tid = threadIdx.x;
    const int sel = blockIdx.x >> 3;
    const float* W = (sel == 0) ? Wq : (sel == 1) ? Wk : Wv;
    const float* bias = (sel == 0) ? bq : (sel == 1) ? bk : bv;
    float* C = (sel == 0) ? Cq : (sel == 1) ? Ck : Cv;
    const int m0 = blockIdx.y * 128, n0 = (blockIdx.x & 7) * 128;
    const int lrow = tid >> 1, lk = (tid & 1) * 8;
    const int lane = tid & 31, wid = tid >> 5;
    const int mBase = (wid >> 1) * 32, nBase = (wid & 1) * 64;
    const int gid = lane >> 2, tig = lane & 3;

    float acc[2][8][4];
#pragma unroll
    for (int i = 0; i < 2; i++)
#pragma unroll
        for (int j = 0; j < 8; j++)
#pragma unroll
            for (int c = 0; c < 4; c++) acc[i][j][c] = 0.f;

    const float* Arow = A + (size_t)(m0 + lrow) * Dc + lk;
    const float* Wrow = W + (size_t)(n0 + lrow) * Dc + lk;

    float4 sa0, sa1, sb0, sb1;
    sa0 = *(const float4*)(Arow + 0);
    sa1 = *(const float4*)(Arow + 4);
    sb0 = *(const float4*)(Wrow + 0);
    sb1 = *(const float4*)(Wrow + 4);
    {
        float* as = &As[0][lk][lrow];
        as[0 * 136] = sa0.x; as[1 * 136] = sa0.y; as[2 * 136] = sa0.z; as[3 * 136] = sa0.w;
        as[4 * 136] = sa1.x; as[5 * 136] = sa1.y; as[6 * 136] = sa1.z; as[7 * 136] = sa1.w;
        float* bs = &Bs[0][lk][lrow];
        bs[0 * 136] = sb0.x; bs[1 * 136] = sb0.y; bs[2 * 136] = sb0.z; bs[3 * 136] = sb0.w;
        bs[4 * 136] = sb1.x; bs[5 * 136] = sb1.y; bs[6 * 136] = sb1.z; bs[7 * 136] = sb1.w;
    }
    __syncthreads();

    const int nk = Dc / 16;
    for (int kt = 0; kt < nk; kt++) {
        const int cur = kt & 1;
        const bool more = (kt + 1) < nk;
        if (more) {
            const float* ap = Arow + (kt + 1) * 16;
            const float* wp = Wrow + (kt + 1) * 16;
            sa0 = *(const float4*)(ap + 0);
            sa1 = *(const float4*)(ap + 4);
            sb0 = *(const float4*)(wp + 0);
            sb1 = *(const float4*)(wp + 4);
        }
        const float* Ac = &As[cur][0][0];
        const float* Bcp = &Bs[cur][0][0];
#pragma unroll
        for (int k8 = 0; k8 < 16; k8 += 8) {
            uint32_t ah[2][4], al[2][4];
#pragma unroll
            for (int mt = 0; mt < 2; mt++) {
                int r0 = mBase + mt * 16 + gid;
                split_tf32(Ac[(k8 + tig) * 136 + r0],       ah[mt][0], al[mt][0]);
                split_tf32(Ac[(k8 + tig) * 136 + r0 + 8],   ah[mt][1], al[mt][1]);
                split_tf32(Ac[(k8 + tig + 4) * 136 + r0],   ah[mt][2], al[mt][2]);
                split_tf32(Ac[(k8 + tig + 4) * 136 + r0 + 8], ah[mt][3], al[mt][3]);
            }
#pragma unroll
            for (int nt = 0; nt < 8; nt++) {
                int c = nBase + nt * 8 + gid;
                uint32_t bh[2], bl[2];
                split_tf32(Bcp[(k8 + tig) * 136 + c],     bh[0], bl[0]);
                split_tf32(Bcp[(k8 + 4 + tig) * 136 + c], bh[1], bl[1]);
#pragma unroll
                for (int mt = 0; mt < 2; mt++) {
                    mma8(acc[mt][nt], ah[mt], bh);
                    mma8(acc[mt][nt], ah[mt], bl);
                    mma8(acc[mt][nt], al[mt], bh);
                }
            }
        }
        if (more) {
            const int nb = cur ^ 1;
            float* as = &As[nb][lk][lrow];
            as[0 * 136] = sa0.x; as[1 * 136] = sa0.y; as[2 * 136] = sa0.z; as[3 * 136] = sa0.w;
            as[4 * 136] = sa1.x; as[5 * 136] = sa1.y; as[6 * 136] = sa1.z; as[7 * 136] = sa1.w;
            float* bs = &Bs[nb][lk][lrow];
            bs[0 * 136] = sb0.x; bs[1 * 136] = sb0.y; bs[2 * 136] = sb0.z; bs[3 * 136] = sb0.w;
            bs[4 * 136] = sb1.x; bs[5 * 136] = sb1.y; bs[6 * 136] = sb1.z; bs[7 * 136] = sb1.w;
            __syncthreads();
        }
    }

#pragma unroll
    for (int mt = 0; mt < 2; mt++) {
        int r = m0 + mBase + mt * 16 + gid;
#pragma unroll
        for (int nt = 0; nt < 8; nt++) {
            int c = n0 + nBase + nt * 8 + 2 * tig;
            float b0v = bias[c], b1v = bias[c + 1];
            *(float2*)(C + (size_t)r * Dc + c) =
                make_float2(acc[mt][nt][0] + b0v, acc[mt][nt][1] + b1v);
            *(float2*)(C + (size_t)(r + 8) * Dc + c) =
                make_float2(acc[mt][nt][2] + b0v, acc[mt][nt][3] + b1v);
        }
    }
}

// ============================================================
// Generic C[M,N] = A[M,K] @ W[N,K]^T (+bias).  (pos + out projections)
// ============================================================
__global__ __launch_bounds__(256, 1) void gemm_tc_nt(
    const float* __restrict__ A, const float* __restrict__ W,
    const float* __restrict__ bias, float* __restrict__ C,
    int M, int N, int K) {
    __shared__ float As[2][16][136];
    __shared__ float Bs[2][16][136];
    const int tid = threadIdx.x;
    const int m0 = blockIdx.y * 128, n0 = blockIdx.x * 128;
    const int lrow = tid >> 1, lk = (tid & 1) * 8;
    const int lane = tid & 31, wid = tid >> 5;
    const int mBase = (wid >> 1) * 32, nBase = (wid & 1) * 64;
    const int gid = lane >> 2, tig = lane & 3;

    float acc[2][8][4];
#pragma unroll
    for (int i = 0; i < 2; i++)
#pragma unroll
        for (int j = 0; j < 8; j++)
#pragma unroll
            for (int c = 0; c < 4; c++) acc[i][j][c] = 0.f;

    const bool aval = (m0 + lrow) < M;
    const bool wval = (n0 + lrow) < N;
    const float* Arow = A + (size_t)(m0 + lrow) * K + lk;
    const float* Wrow = W + (size_t)(n0 + lrow) * K + lk;
    const float4 f4z = make_float4(0.f, 0.f, 0.f, 0.f);

    float4 sa0, sa1, sb0, sb1;
    sa0 = aval ? *(const float4*)(Arow + 0) : f4z;
    sa1 = aval ? *(const float4*)(Arow + 4) : f4z;
    sb0 = wval ? *(const float4*)(Wrow + 0) : f4z;
    sb1 = wval ? *(const float4*)(Wrow + 4) : f4z;
    {
        float* as = &As[0][lk][lrow];
        as[0 * 136] = sa0.x; as[1 * 136] = sa0.y; as[2 * 136] = sa0.z; as[3 * 136] = sa0.w;
        as[4 * 136] = sa1.x; as[5 * 136] = sa1.y; as[6 * 136] = sa1.z; as[7 * 136] = sa1.w;
        float* bs = &Bs[0][lk][lrow];
        bs[0 * 136] = sb0.x; bs[1 * 136] = sb0.y; bs[2 * 136] = sb0.z; bs[3 * 136] = sb0.w;
        bs[4 * 136] = sb1.x; bs[5 * 136] = sb1.y; bs[6 * 136] = sb1.z; bs[7 * 136] = sb1.w;
    }
    __syncthreads();

    const int nk = K / 16;
    for (int kt = 0; kt < nk; kt++) {
        const int cur = kt & 1;
        const bool more = (kt + 1) < nk;
        if (more) {
            const float* ap = Arow + (kt + 1) * 16;
            const float* wp = Wrow + (kt + 1) * 16;
            sa0 = aval ? *(const float4*)(ap + 0) : f4z;
            sa1 = aval ? *(const float4*)(ap + 4) : f4z;
            sb0 = wval ? *(const float4*)(wp + 0) : f4z;
            sb1 = wval ? *(const float4*)(wp + 4) : f4z;
        }
        const float* Ac = &As[cur][0][0];
        const float* Bcp = &Bs[cur][0][0];
#pragma unroll
        for (int k8 = 0; k8 < 16; k8 += 8) {
            uint32_t ah[2][4], al[2][4];
#pragma unroll
            for (int mt = 0; mt < 2; mt++) {
                int r0 = mBase + mt * 16 + gid;
                split_tf32(Ac[(k8 + tig) * 136 + r0],       ah[mt][0], al[mt][0]);
                split_tf32(Ac[(k8 + tig) * 136 + r0 + 8],   ah[mt][1], al[mt][1]);
                split_tf32(Ac[(k8 + tig + 4) * 136 + r0],   ah[mt][2], al[mt][2]);
                split_tf32(Ac[(k8 + tig + 4) * 136 + r0 + 8], ah[mt][3], al[mt][3]);
            }
#pragma unroll
            for (int nt = 0; nt < 8; nt++) {
                int c = nBase + nt * 8 + gid;
                uint32_t bh[2], bl[2];
                split_tf32(Bcp[(k8 + tig) * 136 + c],     bh[0], bl[0]);
                split_tf32(Bcp[(k8 + 4 + tig) * 136 + c], bh[1], bl[1]);
#pragma unroll
                for (int mt = 0; mt < 2; mt++) {
                    mma8(acc[mt][nt], ah[mt], bh);
                    mma8(acc[mt][nt], ah[mt], bl);
                    mma8(acc[mt][nt], al[mt], bh);
                }
            }
        }
        if (more) {
            const int nb = cur ^ 1;
            float* as = &As[nb][lk][lrow];
            as[0 * 136] = sa0.x; as[1 * 136] = sa0.y; as[2 * 136] = sa0.z; as[3 * 136] = sa0.w;
            as[4 * 136] = sa1.x; as[5 * 136] = sa1.y; as[6 * 136] = sa1.z; as[7 * 136] = sa1.w;
            float* bs = &Bs[nb][lk][lrow];
            bs[0 * 136] = sb0.x; bs[1 * 136] = sb0.y; bs[2 * 136] = sb0.z; bs[3 * 136] = sb0.w;
            bs[4 * 136] = sb1.x; bs[5 * 136] = sb1.y; bs[6 * 136] = sb1.z; bs[7 * 136] = sb1.w;
            __syncthreads();
        }
    }

#pragma unroll
    for (int mt = 0; mt < 2; mt++) {
        int r = m0 + mBase + mt * 16 + gid;
#pragma unroll
        for (int nt = 0; nt < 8; nt++) {
            int c = n0 + nBase + nt * 8 + 2 * tig;
            float b0v = bias ? bias[c] : 0.f;
            float b1v = bias ? bias[c + 1] : 0.f;
            if (r < M)
                *(float2*)(C + (size_t)r * N + c) =
                    make_float2(acc[mt][nt][0] + b0v, acc[mt][nt][1] + b1v);
            if (r + 8 < M)
                *(float2*)(C + (size_t)(r + 8) * N + c) =
                    make_float2(acc[mt][nt][2] + b0v, acc[mt][nt][3] + b1v);
        }
    }
}

// ============================================================
// FUSED attention: per block = (bh, 32 q-rows):
//   Sb[32][1024] = (q+u)K^T ; Sb += band((q+v)P^T) ; softmax(Sb/8) ;
//   probs <- Sb (single gmem write) ; ctx = Sb @ V.
// smem: Sb 32x1028 | Au 64x40 | Av 64x40 | Bt 64x72   (170.5 KB dyn)
// ============================================================
#define SB_STR 1028
#define SB_FLOATS (32 * SB_STR)
#define AU_OFF SB_FLOATS
#define AV_OFF (AU_OFF + 64 * 40)
#define BT_OFF (AV_OFF + 64 * 40)
#define FUSED_SMEM_BYTES ((BT_OFF + 64 * 72) * 4)

__global__ __launch_bounds__(256, 1) void fused_attn(
    const float* __restrict__ Q, const float* __restrict__ K,
    const float* __restrict__ P, const float* __restrict__ V,
    const float* __restrict__ u, const float* __restrict__ vb,
    float* __restrict__ probs, float* __restrict__ ctx) {
    extern __shared__ float sm[];
    float* Sb = sm;
    float* Au = sm + AU_OFF;
    float* Av = sm + AV_OFF;
    float* Bt = sm + BT_OFF;

    const int t = threadIdx.x;
    const int bh = blockIdx.y, zb = bh >> 4, h = bh & 15;
    const int q0 = blockIdx.x * 32;
    const int lane = t & 31, w = t >> 5;
    const int mB = (w & 1) * 16, nB = (w >> 1) * 16;
    const int gid = lane >> 2, tig = lane & 3;

    // ---- load q tile (32x64), build q+u and q+v transposed [d][m] ----
    {
        int qr = t >> 3;             // 0..31
        int dB = (t & 7) * 8;        // 0..56
        const float* qp = Q + ((size_t)(zb * Tc) + q0 + qr) * Dc + h * HSc + dB;
        float4 a0 = *(const float4*)(qp + 0), a1 = *(const float4*)(qp + 4);
        const float* up = u + h * HSc + dB;
        const float* vp = vb + h * HSc + dB;
        float4 u0 = *(const float4*)(up + 0), u1 = *(const float4*)(up + 4);
        float4 v0 = *(const float4*)(vp + 0), v1 = *(const float4*)(vp + 4);
        Au[(dB + 0) * 40 + qr] = a0.x + u0.x; Av[(dB + 0) * 40 + qr] = a0.x + v0.x;
        Au[(dB + 1) * 40 + qr] = a0.y + u0.y; Av[(dB + 1) * 40 + qr] = a0.y + v0.y;
        Au[(dB + 2) * 40 + qr] = a0.z + u0.z; Av[(dB + 2) * 40 + qr] = a0.z + v0.z;
        Au[(dB + 3) * 40 + qr] = a0.w + u0.w; Av[(dB + 3) * 40 + qr] = a0.w + v0.w;
        Au[(dB + 4) * 40 + qr] = a1.x + u1.x; Av[(dB + 4) * 40 + qr] = a1.x + v1.x;
        Au[(dB + 5) * 40 + qr] = a1.y + u1.y; Av[(dB + 5) * 40 + qr] = a1.y + v1.y;
        Au[(dB + 6) * 40 + qr] = a1.z + u1.z; Av[(dB + 6) * 40 + qr] = a1.z + v1.z;
        Au[(dB + 7) * 40 + qr] = a1.w + u1.w; Av[(dB + 7) * 40 + qr] = a1.w + v1.w;
    }

    const int kr = t >> 2;           // 0..63
    const int dB2 = (t & 3) * 16;    // 0..48

    // ================= phase 1: ac = (q+u) K^T  =================
    for (int j0 = 0; j0 < Tc; j0 += 64) {
        const float* kp = K + ((size_t)(zb * Tc) + j0 + kr) * Dc + h * HSc + dB2;
        float4 r0 = *(const float4*)(kp + 0), r1 = *(const float4*)(kp + 4);
        float4 r2 = *(const float4*)(kp + 8), r3 = *(const float4*)(kp + 12);
        __syncthreads();
        Bt[(dB2 + 0) * 72 + kr] = r0.x; Bt[(dB2 + 1) * 72 + kr] = r0.y;
        Bt[(dB2 + 2) * 72 + kr] = r0.z; Bt[(dB2 + 3) * 72 + kr] = r0.w;
        Bt[(dB2 + 4) * 72 + kr] = r1.x; Bt[(dB2 + 5) * 72 + kr] = r1.y;
        Bt[(dB2 + 6) * 72 + kr] = r1.z; Bt[(dB2 + 7) * 72 + kr] = r1.w;
        Bt[(dB2 + 8) * 72 + kr] = r2.x; Bt[(dB2 + 9) * 72 + kr] = r2.y;
        Bt[(dB2 + 10) * 72 + kr] = r2.z; Bt[(dB2 + 11) * 72 + kr] = r2.w;
        Bt[(dB2 + 12) * 72 + kr] = r3.x; Bt[(dB2 + 13) * 72 + kr] = r3.y;
        Bt[(dB2 + 14) * 72 + kr] = r3.z; Bt[(dB2 + 15) * 72 + kr] = r3.w;
        __syncthreads();

        float acc[2][4] = {{0.f, 0.f, 0.f, 0.f}, {0.f, 0.f, 0.f, 0.f}};
#pragma unroll
        for (int k8 = 0; k8 < 64; k8 += 8) {
            uint32_t ah[4], al[4];
            split_tf32(Au[(k8 + tig) * 40 + mB + gid],         ah[0], al[0]);
            split_tf32(Au[(k8 + tig) * 40 + mB + gid + 8],     ah[1], al[1]);
            split_tf32(Au[(k8 + tig + 4) * 40 + mB + gid],     ah[2], al[2]);
            split_tf32(Au[(k8 + tig + 4) * 40 + mB + gid + 8], ah[3], al[3]);
#pragma unroll
            for (int nt = 0; nt < 2; nt++) {
                int c = nB + nt * 8 + gid;
                mma_grp(acc[nt], ah, al, Bt[(k8 + tig) * 72 + c], Bt[(k8 + 4 + tig) * 72 + c]);
            }
        }
#pragma unroll
        for (int nt = 0; nt < 2; nt++) {
            int col = j0 + nB + nt * 8 + 2 * tig;
            *(float2*)&Sb[(mB + gid) * SB_STR + col] = make_float2(acc[nt][0], acc[nt][1]);
            *(float2*)&Sb[(mB + gid + 8) * SB_STR + col] = make_float2(acc[nt][2], acc[nt][3]);
        }
    }

    // ================= phase 2: bd band, scatter-add =================
    const int lStart = (Tc - 1) - (q0 + 31);   // >= 0
    for (int it = 0; it < 17; it++) {
        int lBase = lStart + it * 64;
        int l = lBase + kr;
        float4 r0, r1, r2, r3;
        if (l < Lc) {
            const float* pp = P + (size_t)l * Dc + h * HSc + dB2;
            r0 = *(const float4*)(pp + 0); r1 = *(const float4*)(pp + 4);
            r2 = *(const float4*)(pp + 8); r3 = *(const float4*)(pp + 12);
        } else {
            r0 = r1 = r2 = r3 = make_float4(0.f, 0.f, 0.f, 0.f);
        }
        __syncthreads();
        Bt[(dB2 + 0) * 72 + kr] = r0.x; Bt[(dB2 + 1) * 72 + kr] = r0.y;
        Bt[(dB2 + 2) * 72 + kr] = r0.z; Bt[(dB2 + 3) * 72 + kr] = r0.w;
        Bt[(dB2 + 4) * 72 + kr] = r1.x; Bt[(dB2 + 5) * 72 + kr] = r1.y;
        Bt[(dB2 + 6) * 72 + kr] = r1.z; Bt[(dB2 + 7) * 72 + kr] = r1.w;
        Bt[(dB2 + 8) * 72 + kr] = r2.x; Bt[(dB2 + 9) * 72 + kr] = r2.y;
        Bt[(dB2 + 10) * 72 + kr] = r2.z; Bt[(dB2 + 11) * 72 + kr] = r2.w;
        Bt[(dB2 + 12) * 72 + kr] = r3.x; Bt[(dB2 + 13) * 72 + kr] = r3.y;
        Bt[(dB2 + 14) * 72 + kr] = r3.z; Bt[(dB2 + 15) * 72 + kr] = r3.w;
        __syncthreads();

        float acc[2][4] = {{0.f, 0.f, 0.f, 0.f}, {0.f, 0.f, 0.f, 0.f}};
#pragma unroll
        for (int k8 = 0; k8 < 64; k8 += 8) {
            uint32_t ah[4], al[4];
            split_tf32(Av[(k8 + tig) * 40 + mB + gid],         ah[0], al[0]);
            split_tf32(Av[(k8 + tig) * 40 + mB + gid + 8],     ah[1], al[1]);
            split_tf32(Av[(k8 + tig + 4) * 40 + mB + gid],     ah[2], al[2]);
            split_tf32(Av[(k8 + tig + 4) * 40 + mB + gid + 8], ah[3], al[3]);
#pragma unroll
            for (int nt = 0; nt < 2; nt++) {
                int c = nB + nt * 8 + gid;
                mma_grp(acc[nt], ah, al, Bt[(k8 + tig) * 72 + c], Bt[(k8 + 4 + tig) * 72 + c]);
            }
        }
#pragma unroll
        for (int nt = 0; nt < 2; nt++) {
            int lc = lBase + nB + nt * 8 + 2 * tig;
            int m = mB + gid;
            int j = (q0 + m) + lc - (Tc - 1);
            if (j >= 0 && j < Tc) Sb[m * SB_STR + j] += acc[nt][0];
            if (j + 1 >= 0 && j + 1 < Tc) Sb[m * SB_STR + j + 1] += acc[nt][1];
            int j2 = j + 8;
            if (j2 >= 0 && j2 < Tc) Sb[(m + 8) * SB_STR + j2] += acc[nt][2];
            if (j2 + 1 >= 0 && j2 + 1 < Tc) Sb[(m + 8) * SB_STR + j2 + 1] += acc[nt][3];
        }
    }
    __syncthreads();

    // ================= phase 3: softmax (scale 0.125) =================
    {
#pragma unroll
        for (int rr = 0; rr < 4; rr++) {
            float* row = Sb + (w * 4 + rr) * SB_STR;
            float mx = -3.4e38f;
            for (int c = lane; c < Tc; c += 32) mx = fmaxf(mx, row[c]);
#pragma unroll
            for (int o = 16; o; o >>= 1) mx = fmaxf(mx, __shfl_xor_sync(0xffffffffu, mx, o));
            float sum = 0.f;
            for (int c = lane; c < Tc; c += 32) {
                float e = expf(0.125f * (row[c] - mx));
                row[c] = e;
                sum += e;
            }
#pragma unroll
            for (int o = 16; o; o >>= 1) sum += __shfl_xor_sync(0xffffffffu, sum, o);
            float inv = 1.f / sum;
            for (int c = lane; c < Tc; c += 32) row[c] *= inv;
        }
    }
    __syncthreads();

    // ---- write probs (single pass, coalesced) ----
    {
        float* pb = probs + ((size_t)bh << 20) + (size_t)q0 * Tc;
#pragma unroll 4
        for (int r = 0; r < 32; r++) {
            float4 val = *(float4*)&Sb[r * SB_STR + 4 * t];
            *(float4*)(pb + (size_t)r * Tc + 4 * t) = val;
        }
    }

    // ================= phase 4: ctx = probs @ V =================
    float acc2[2][4] = {{0.f, 0.f, 0.f, 0.f}, {0.f, 0.f, 0.f, 0.f}};
    for (int kc = 0; kc < Tc; kc += 64) {
        const float* vp = V + ((size_t)(zb * Tc) + kc + kr) * Dc + h * HSc + dB2;
        float4 r0 = *(const float4*)(vp + 0), r1 = *(const float4*)(vp + 4);
        float4 r2 = *(const float4*)(vp + 8), r3 = *(const float4*)(vp + 12);
        __syncthreads();
        *(float4*)&Bt[kr * 72 + dB2 + 0] = r0;
        *(float4*)&Bt[kr * 72 + dB2 + 4] = r1;
        *(float4*)&Bt[kr * 72 + dB2 + 8] = r2;
        *(float4*)&Bt[kr * 72 + dB2 + 12] = r3;
        __syncthreads();

#pragma unroll
        for (int k8 = 0; k8 < 64; k8 += 8) {
            uint32_t ah[4], al[4];
            const float* arow = Sb + (mB + gid) * SB_STR + kc;
            const float* arow8 = arow + 8 * SB_STR;
            split_tf32(arow[k8 + tig],      ah[0], al[0]);
            split_tf32(arow8[k8 + tig],     ah[1], al[1]);
            split_tf32(arow[k8 + tig + 4],  ah[2], al[2]);
            split_tf32(arow8[k8 + tig + 4], ah[3], al[3]);
#pragma unroll
            for (int nt = 0; nt < 2; nt++) {
                int c = nB + nt * 8 + gid;
                mma_grp(acc2[nt], ah, al, Bt[(k8 + tig) * 72 + c], Bt[(k8 + 4 + tig) * 72 + c]);
            }
        }
    }
    {
        int r = q0 + mB + gid;
#pragma unroll
        for (int nt = 0; nt < 2; nt++) {
            int c = nB + nt * 8 + 2 * tig;
            *(float2*)(ctx + ((size_t)(zb * Tc) + r) * Dc + h * HSc + c) =
                make_float2(acc2[nt][0], acc2[nt][1]);
            *(float2*)(ctx + ((size_t)(zb * Tc) + r + 8) * Dc + h * HSc + c) =
                make_float2(acc2[nt][2], acc2[nt][3]);
        }
    }
}

// ============================================================
extern "C" void kernel_launch(void* const* d_in, const int* in_sizes, int n_in,
                              void* d_out, int out_size) {
    const float* hs  = (const float*)d_in[0];
    const float* rpe = (const float*)d_in[1];
    const float* Wq  = (const float*)d_in[2];
    const float* bq  = (const float*)d_in[3];
    const float* Wk  = (const float*)d_in[4];
    const float* bk  = (const float*)d_in[5];
    const float* Wv  = (const float*)d_in[6];
    const float* bv  = (const float*)d_in[7];
    const float* Wo  = (const float*)d_in[8];
    const float* bo  = (const float*)d_in[9];
    const float* Wp  = (const float*)d_in[10];
    const float* pu  = (const float*)d_in[11];
    const float* pvb = (const float*)d_in[12];

    float* out = (float*)d_out;                 // (B,T,D)
    float* S   = out + (size_t)Bc * Tc * Dc;    // (B,H,T,T) probs

    float *pq, *pk, *pv, *pp, *pctx;
    cudaGetSymbolAddress((void**)&pq,   g_q);
    cudaGetSymbolAddress((void**)&pk,   g_k);
    cudaGetSymbolAddress((void**)&pv,   g_v);
    cudaGetSymbolAddress((void**)&pp,   g_p);
    cudaGetSymbolAddress((void**)&pctx, g_ctx);

    cudaFuncSetAttribute(fused_attn, cudaFuncAttributeMaxDynamicSharedMemorySize,
                         FUSED_SMEM_BYTES);

    dim3 thr(256);
    gemm_qkv<<<dim3(24, 32), thr>>>(hs, Wq, Wk, Wv, bq, bk, bv, pq, pk, pv);
    gemm_tc_nt<<<dim3(8, 16), thr>>>(rpe, Wp, nullptr, pp, Lc, Dc, Dc);

    fused_attn<<<dim3(Tc / 32, Bc * Hc), thr, FUSED_SMEM_BYTES>>>(
        pq, pk, pp, pv, pu, pvb, S, pctx);

    gemm_tc_nt<<<dim3(8, 32), thr>>>(pctx, Wo, bo, out, Bc * Tc, Dc, Dc);
}

// round 4
// speedup vs baseline: 1.5965x; 1.5030x over previous
#include <cuda_runtime.h>
#include <math.h>
#include <stdint.h>

#define Bc 4
#define Tc 1024
#define Dc 1024
#define Hc 16
#define HSc 64
#define Lc 2047

// -------- scratch (static device globals; no allocations allowed) --------
__device__ float g_q[Bc * Tc * Dc];
__device__ float g_k[Bc * Tc * Dc];
__device__ float g_v[Bc * Tc * Dc];
__device__ float g_p[Lc * Dc];
__device__ float g_ctx[Bc * Tc * Dc];

// ============================================================
// tf32 helpers (plain tf32: single MMA, round-to-nearest)
// ============================================================
__device__ __forceinline__ uint32_t tf32_of(float x) {
    uint32_t r;
    asm("cvt.rna.tf32.f32 %0, %1;" : "=r"(r) : "f"(x));
    return r;
}
__device__ __forceinline__ void mma8(float* d, const uint32_t* a, const uint32_t* b) {
    asm volatile(
        "mma.sync.aligned.m16n8k8.row.col.f32.tf32.tf32.f32 "
        "{%0,%1,%2,%3},{%4,%5,%6,%7},{%8,%9},{%0,%1,%2,%3};"
        : "+f"(d[0]), "+f"(d[1]), "+f"(d[2]), "+f"(d[3])
        : "r"(a[0]), "r"(a[1]), "r"(a[2]), "r"(a[3]), "r"(b[0]), "r"(b[1]));
}
__device__ __forceinline__ void mma1(float* acc, const uint32_t a[4], float b0f, float b1f) {
    uint32_t b[2];
    b[0] = tf32_of(b0f);
    b[1] = tf32_of(b1f);
    mma8(acc, a, b);
}

// ============================================================
// Fused QKV projection: C{q,k,v}[4096,1024] = hs @ W{q,k,v}^T + b
// 128x128 block, BK=16, double buffered. grid (24, 32).
// ============================================================
__global__ __launch_bounds__(256, 2) void gemm_qkv(
    const float* __restrict__ A,
    const float* __restrict__ Wq, const float* __restrict__ Wk, const float* __restrict__ Wv,
    const float* __restrict__ bq, const float* __restrict__ bk, const float* __restrict__ bv,
    float* __restrict__ Cq, float* __restrict__ Ck, float* __restrict__ Cv) {
    __shared__ float As[2][16][136];
    __shared__ float Bs[2][16][136];
    const int tid = threadIdx.x;
    const int sel = blockIdx.x >> 3;
    const float* W = (sel == 0) ? Wq : (sel == 1) ? Wk : Wv;
    const float* bias = (sel == 0) ? bq : (sel == 1) ? bk : bv;
    float* C = (sel == 0) ? Cq : (sel == 1) ? Ck : Cv;
    const int m0 = blockIdx.y * 128, n0 = (blockIdx.x & 7) * 128;
    const int lrow = tid >> 1, lk = (tid & 1) * 8;
    const int lane = tid & 31, wid = tid >> 5;
    const int mBase = (wid >> 1) * 32, nBase = (wid & 1) * 64;
    const int gid = lane >> 2, tig = lane & 3;

    float acc[2][8][4];
#pragma unroll
    for (int i = 0; i < 2; i++)
#pragma unroll
        for (int j = 0; j < 8; j++)
#pragma unroll
            for (int c = 0; c < 4; c++) acc[i][j][c] = 0.f;

    const float* Arow = A + (size_t)(m0 + lrow) * Dc + lk;
    const float* Wrow = W + (size_t)(n0 + lrow) * Dc + lk;

    float4 sa0, sa1, sb0, sb1;
    sa0 = *(const float4*)(Arow + 0);
    sa1 = *(const float4*)(Arow + 4);
    sb0 = *(const float4*)(Wrow + 0);
    sb1 = *(const float4*)(Wrow + 4);
    {
        float* as = &As[0][lk][lrow];
        as[0 * 136] = sa0.x; as[1 * 136] = sa0.y; as[2 * 136] = sa0.z; as[3 * 136] = sa0.w;
        as[4 * 136] = sa1.x; as[5 * 136] = sa1.y; as[6 * 136] = sa1.z; as[7 * 136] = sa1.w;
        float* bs = &Bs[0][lk][lrow];
        bs[0 * 136] = sb0.x; bs[1 * 136] = sb0.y; bs[2 * 136] = sb0.z; bs[3 * 136] = sb0.w;
        bs[4 * 136] = sb1.x; bs[5 * 136] = sb1.y; bs[6 * 136] = sb1.z; bs[7 * 136] = sb1.w;
    }
    __syncthreads();

    const int nk = Dc / 16;
    for (int kt = 0; kt < nk; kt++) {
        const int cur = kt & 1;
        const bool more = (kt + 1) < nk;
        if (more) {
            const float* ap = Arow + (kt + 1) * 16;
            const float* wp = Wrow + (kt + 1) * 16;
            sa0 = *(const float4*)(ap + 0);
            sa1 = *(const float4*)(ap + 4);
            sb0 = *(const float4*)(wp + 0);
            sb1 = *(const float4*)(wp + 4);
        }
        const float* Ac = &As[cur][0][0];
        const float* Bcp = &Bs[cur][0][0];
#pragma unroll
        for (int k8 = 0; k8 < 16; k8 += 8) {
            uint32_t ah[2][4];
#pragma unroll
            for (int mt = 0; mt < 2; mt++) {
                int r0 = mBase + mt * 16 + gid;
                ah[mt][0] = tf32_of(Ac[(k8 + tig) * 136 + r0]);
                ah[mt][1] = tf32_of(Ac[(k8 + tig) * 136 + r0 + 8]);
                ah[mt][2] = tf32_of(Ac[(k8 + tig + 4) * 136 + r0]);
                ah[mt][3] = tf32_of(Ac[(k8 + tig + 4) * 136 + r0 + 8]);
            }
#pragma unroll
            for (int nt = 0; nt < 8; nt++) {
                int c = nBase + nt * 8 + gid;
                uint32_t bh[2];
                bh[0] = tf32_of(Bcp[(k8 + tig) * 136 + c]);
                bh[1] = tf32_of(Bcp[(k8 + 4 + tig) * 136 + c]);
#pragma unroll
                for (int mt = 0; mt < 2; mt++) mma8(acc[mt][nt], ah[mt], bh);
            }
        }
        if (more) {
            const int nb = cur ^ 1;
            float* as = &As[nb][lk][lrow];
            as[0 * 136] = sa0.x; as[1 * 136] = sa0.y; as[2 * 136] = sa0.z; as[3 * 136] = sa0.w;
            as[4 * 136] = sa1.x; as[5 * 136] = sa1.y; as[6 * 136] = sa1.z; as[7 * 136] = sa1.w;
            float* bs = &Bs[nb][lk][lrow];
            bs[0 * 136] = sb0.x; bs[1 * 136] = sb0.y; bs[2 * 136] = sb0.z; bs[3 * 136] = sb0.w;
            bs[4 * 136] = sb1.x; bs[5 * 136] = sb1.y; bs[6 * 136] = sb1.z; bs[7 * 136] = sb1.w;
            __syncthreads();
        }
    }

#pragma unroll
    for (int mt = 0; mt < 2; mt++) {
        int r = m0 + mBase + mt * 16 + gid;
#pragma unroll
        for (int nt = 0; nt < 8; nt++) {
            int c = n0 + nBase + nt * 8 + 2 * tig;
            float b0v = bias[c], b1v = bias[c + 1];
            *(float2*)(C + (size_t)r * Dc + c) =
                make_float2(acc[mt][nt][0] + b0v, acc[mt][nt][1] + b1v);
            *(float2*)(C + (size_t)(r + 8) * Dc + c) =
                make_float2(acc[mt][nt][2] + b0v, acc[mt][nt][3] + b1v);
        }
    }
}

// ============================================================
// Generic C[M,N] = A[M,K] @ W[N,K]^T (+bias).  (pos + out projections)
// ============================================================
__global__ __launch_bounds__(256, 2) void gemm_tc_nt(
    const float* __restrict__ A, const float* __restrict__ W,
    const float* __restrict__ bias, float* __restrict__ C,
    int M, int N, int K) {
    __shared__ float As[2][16][136];
    __shared__ float Bs[2][16][136];
    const int tid = threadIdx.x;
    const int m0 = blockIdx.y * 128, n0 = blockIdx.x * 128;
    const int lrow = tid >> 1, lk = (tid & 1) * 8;
    const int lane = tid & 31, wid = tid >> 5;
    const int mBase = (wid >> 1) * 32, nBase = (wid & 1) * 64;
    const int gid = lane >> 2, tig = lane & 3;

    float acc[2][8][4];
#pragma unroll
    for (int i = 0; i < 2; i++)
#pragma unroll
        for (int j = 0; j < 8; j++)
#pragma unroll
            for (int c = 0; c < 4; c++) acc[i][j][c] = 0.f;

    const bool aval = (m0 + lrow) < M;
    const bool wval = (n0 + lrow) < N;
    const float* Arow = A + (size_t)(m0 + lrow) * K + lk;
    const float* Wrow = W + (size_t)(n0 + lrow) * K + lk;
    const float4 f4z = make_float4(0.f, 0.f, 0.f, 0.f);

    float4 sa0, sa1, sb0, sb1;
    sa0 = aval ? *(const float4*)(Arow + 0) : f4z;
    sa1 = aval ? *(const float4*)(Arow + 4) : f4z;
    sb0 = wval ? *(const float4*)(Wrow + 0) : f4z;
    sb1 = wval ? *(const float4*)(Wrow + 4) : f4z;
    {
        float* as = &As[0][lk][lrow];
        as[0 * 136] = sa0.x; as[1 * 136] = sa0.y; as[2 * 136] = sa0.z; as[3 * 136] = sa0.w;
        as[4 * 136] = sa1.x; as[5 * 136] = sa1.y; as[6 * 136] = sa1.z; as[7 * 136] = sa1.w;
        float* bs = &Bs[0][lk][lrow];
        bs[0 * 136] = sb0.x; bs[1 * 136] = sb0.y; bs[2 * 136] = sb0.z; bs[3 * 136] = sb0.w;
        bs[4 * 136] = sb1.x; bs[5 * 136] = sb1.y; bs[6 * 136] = sb1.z; bs[7 * 136] = sb1.w;
    }
    __syncthreads();

    const int nk = K / 16;
    for (int kt = 0; kt < nk; kt++) {
        const int cur = kt & 1;
        const bool more = (kt + 1) < nk;
        if (more) {
            const float* ap = Arow + (kt + 1) * 16;
            const float* wp = Wrow + (kt + 1) * 16;
            sa0 = aval ? *(const float4*)(ap + 0) : f4z;
            sa1 = aval ? *(const float4*)(ap + 4) : f4z;
            sb0 = wval ? *(const float4*)(wp + 0) : f4z;
            sb1 = wval ? *(const float4*)(wp + 4) : f4z;
        }
        const float* Ac = &As[cur][0][0];
        const float* Bcp = &Bs[cur][0][0];
#pragma unroll
        for (int k8 = 0; k8 < 16; k8 += 8) {
            uint32_t ah[2][4];
#pragma unroll
            for (int mt = 0; mt < 2; mt++) {
                int r0 = mBase + mt * 16 + gid;
                ah[mt][0] = tf32_of(Ac[(k8 + tig) * 136 + r0]);
                ah[mt][1] = tf32_of(Ac[(k8 + tig) * 136 + r0 + 8]);
                ah[mt][2] = tf32_of(Ac[(k8 + tig + 4) * 136 + r0]);
                ah[mt][3] = tf32_of(Ac[(k8 + tig + 4) * 136 + r0 + 8]);
            }
#pragma unroll
            for (int nt = 0; nt < 8; nt++) {
                int c = nBase + nt * 8 + gid;
                uint32_t bh[2];
                bh[0] = tf32_of(Bcp[(k8 + tig) * 136 + c]);
                bh[1] = tf32_of(Bcp[(k8 + 4 + tig) * 136 + c]);
#pragma unroll
                for (int mt = 0; mt < 2; mt++) mma8(acc[mt][nt], ah[mt], bh);
            }
        }
        if (more) {
            const int nb = cur ^ 1;
            float* as = &As[nb][lk][lrow];
            as[0 * 136] = sa0.x; as[1 * 136] = sa0.y; as[2 * 136] = sa0.z; as[3 * 136] = sa0.w;
            as[4 * 136] = sa1.x; as[5 * 136] = sa1.y; as[6 * 136] = sa1.z; as[7 * 136] = sa1.w;
            float* bs = &Bs[nb][lk][lrow];
            bs[0 * 136] = sb0.x; bs[1 * 136] = sb0.y; bs[2 * 136] = sb0.z; bs[3 * 136] = sb0.w;
            bs[4 * 136] = sb1.x; bs[5 * 136] = sb1.y; bs[6 * 136] = sb1.z; bs[7 * 136] = sb1.w;
            __syncthreads();
        }
    }

#pragma unroll
    for (int mt = 0; mt < 2; mt++) {
        int r = m0 + mBase + mt * 16 + gid;
#pragma unroll
        for (int nt = 0; nt < 8; nt++) {
            int c = n0 + nBase + nt * 8 + 2 * tig;
            float b0v = bias ? bias[c] : 0.f;
            float b1v = bias ? bias[c + 1] : 0.f;
            if (r < M)
                *(float2*)(C + (size_t)r * N + c) =
                    make_float2(acc[mt][nt][0] + b0v, acc[mt][nt][1] + b1v);
            if (r + 8 < M)
                *(float2*)(C + (size_t)(r + 8) * N + c) =
                    make_float2(acc[mt][nt][2] + b0v, acc[mt][nt][3] + b1v);
        }
    }
}

// ============================================================
// FUSED attention: per block = (bh, 32 q-rows):
//   Sb[32][1024] = (q+u)K^T ; Sb += band((q+v)P^T) ; softmax(Sb/8) ;
//   probs <- Sb (single gmem write) ; ctx = Sb @ V.
// ============================================================
#define SB_STR 1028
#define SB_FLOATS (32 * SB_STR)
#define AU_OFF SB_FLOATS
#define AV_OFF (AU_OFF + 64 * 40)
#define BT_OFF (AV_OFF + 64 * 40)
#define FUSED_SMEM_BYTES ((BT_OFF + 64 * 72) * 4)

__global__ __launch_bounds__(256, 1) void fused_attn(
    const float* __restrict__ Q, const float* __restrict__ K,
    const float* __restrict__ P, const float* __restrict__ V,
    const float* __restrict__ u, const float* __restrict__ vb,
    float* __restrict__ probs, float* __restrict__ ctx) {
    extern __shared__ float sm[];
    float* Sb = sm;
    float* Au = sm + AU_OFF;
    float* Av = sm + AV_OFF;
    float* Bt = sm + BT_OFF;

    const int t = threadIdx.x;
    const int bh = blockIdx.y, zb = bh >> 4, h = bh & 15;
    const int q0 = blockIdx.x * 32;
    const int lane = t & 31, w = t >> 5;
    const int mB = (w & 1) * 16, nB = (w >> 1) * 16;
    const int gid = lane >> 2, tig = lane & 3;

    // ---- load q tile (32x64), build q+u and q+v transposed [d][m] ----
    {
        int qr = t >> 3;             // 0..31
        int dB = (t & 7) * 8;        // 0..56
        const float* qp = Q + ((size_t)(zb * Tc) + q0 + qr) * Dc + h * HSc + dB;
        float4 a0 = *(const float4*)(qp + 0), a1 = *(const float4*)(qp + 4);
        const float* up = u + h * HSc + dB;
        const float* vp = vb + h * HSc + dB;
        float4 u0 = *(const float4*)(up + 0), u1 = *(const float4*)(up + 4);
        float4 v0 = *(const float4*)(vp + 0), v1 = *(const float4*)(vp + 4);
        Au[(dB + 0) * 40 + qr] = a0.x + u0.x; Av[(dB + 0) * 40 + qr] = a0.x + v0.x;
        Au[(dB + 1) * 40 + qr] = a0.y + u0.y; Av[(dB + 1) * 40 + qr] = a0.y + v0.y;
        Au[(dB + 2) * 40 + qr] = a0.z + u0.z; Av[(dB + 2) * 40 + qr] = a0.z + v0.z;
        Au[(dB + 3) * 40 + qr] = a0.w + u0.w; Av[(dB + 3) * 40 + qr] = a0.w + v0.w;
        Au[(dB + 4) * 40 + qr] = a1.x + u1.x; Av[(dB + 4) * 40 + qr] = a1.x + v1.x;
        Au[(dB + 5) * 40 + qr] = a1.y + u1.y; Av[(dB + 5) * 40 + qr] = a1.y + v1.y;
        Au[(dB + 6) * 40 + qr] = a1.z + u1.z; Av[(dB + 6) * 40 + qr] = a1.z + v1.z;
        Au[(dB + 7) * 40 + qr] = a1.w + u1.w; Av[(dB + 7) * 40 + qr] = a1.w + v1.w;
    }

    const int kr = t >> 2;           // 0..63
    const int dB2 = (t & 3) * 16;    // 0..48

    // ================= phase 1: ac = (q+u) K^T  =================
    for (int j0 = 0; j0 < Tc; j0 += 64) {
        const float* kp = K + ((size_t)(zb * Tc) + j0 + kr) * Dc + h * HSc + dB2;
        float4 r0 = *(const float4*)(kp + 0), r1 = *(const float4*)(kp + 4);
        float4 r2 = *(const float4*)(kp + 8), r3 = *(const float4*)(kp + 12);
        __syncthreads();
        Bt[(dB2 + 0) * 72 + kr] = r0.x; Bt[(dB2 + 1) * 72 + kr] = r0.y;
        Bt[(dB2 + 2) * 72 + kr] = r0.z; Bt[(dB2 + 3) * 72 + kr] = r0.w;
        Bt[(dB2 + 4) * 72 + kr] = r1.x; Bt[(dB2 + 5) * 72 + kr] = r1.y;
        Bt[(dB2 + 6) * 72 + kr] = r1.z; Bt[(dB2 + 7) * 72 + kr] = r1.w;
        Bt[(dB2 + 8) * 72 + kr] = r2.x; Bt[(dB2 + 9) * 72 + kr] = r2.y;
        Bt[(dB2 + 10) * 72 + kr] = r2.z; Bt[(dB2 + 11) * 72 + kr] = r2.w;
        Bt[(dB2 + 12) * 72 + kr] = r3.x; Bt[(dB2 + 13) * 72 + kr] = r3.y;
        Bt[(dB2 + 14) * 72 + kr] = r3.z; Bt[(dB2 + 15) * 72 + kr] = r3.w;
        __syncthreads();

        float acc[2][4] = {{0.f, 0.f, 0.f, 0.f}, {0.f, 0.f, 0.f, 0.f}};
#pragma unroll
        for (int k8 = 0; k8 < 64; k8 += 8) {
            uint32_t ah[4];
            ah[0] = tf32_of(Au[(k8 + tig) * 40 + mB + gid]);
            ah[1] = tf32_of(Au[(k8 + tig) * 40 + mB + gid + 8]);
            ah[2] = tf32_of(Au[(k8 + tig + 4) * 40 + mB + gid]);
            ah[3] = tf32_of(Au[(k8 + tig + 4) * 40 + mB + gid + 8]);
#pragma unroll
            for (int nt = 0; nt < 2; nt++) {
                int c = nB + nt * 8 + gid;
                mma1(acc[nt], ah, Bt[(k8 + tig) * 72 + c], Bt[(k8 + 4 + tig) * 72 + c]);
            }
        }
#pragma unroll
        for (int nt = 0; nt < 2; nt++) {
            int col = j0 + nB + nt * 8 + 2 * tig;
            *(float2*)&Sb[(mB + gid) * SB_STR + col] = make_float2(acc[nt][0], acc[nt][1]);
            *(float2*)&Sb[(mB + gid + 8) * SB_STR + col] = make_float2(acc[nt][2], acc[nt][3]);
        }
    }

    // ================= phase 2: bd band, scatter-add =================
    const int lStart = (Tc - 1) - (q0 + 31);   // >= 0
    for (int it = 0; it < 17; it++) {
        int lBase = lStart + it * 64;
        int l = lBase + kr;
        float4 r0, r1, r2, r3;
        if (l < Lc) {
            const float* pp = P + (size_t)l * Dc + h * HSc + dB2;
            r0 = *(const float4*)(pp + 0); r1 = *(const float4*)(pp + 4);
            r2 = *(const float4*)(pp + 8); r3 = *(const float4*)(pp + 12);
        } else {
            r0 = r1 = r2 = r3 = make_float4(0.f, 0.f, 0.f, 0.f);
        }
        __syncthreads();
        Bt[(dB2 + 0) * 72 + kr] = r0.x; Bt[(dB2 + 1) * 72 + kr] = r0.y;
        Bt[(dB2 + 2) * 72 + kr] = r0.z; Bt[(dB2 + 3) * 72 + kr] = r0.w;
        Bt[(dB2 + 4) * 72 + kr] = r1.x; Bt[(dB2 + 5) * 72 + kr] = r1.y;
        Bt[(dB2 + 6) * 72 + kr] = r1.z; Bt[(dB2 + 7) * 72 + kr] = r1.w;
        Bt[(dB2 + 8) * 72 + kr] = r2.x; Bt[(dB2 + 9) * 72 + kr] = r2.y;
        Bt[(dB2 + 10) * 72 + kr] = r2.z; Bt[(dB2 + 11) * 72 + kr] = r2.w;
        Bt[(dB2 + 12) * 72 + kr] = r3.x; Bt[(dB2 + 13) * 72 + kr] = r3.y;
        Bt[(dB2 + 14) * 72 + kr] = r3.z; Bt[(dB2 + 15) * 72 + kr] = r3.w;
        __syncthreads();

        float acc[2][4] = {{0.f, 0.f, 0.f, 0.f}, {0.f, 0.f, 0.f, 0.f}};
#pragma unroll
        for (int k8 = 0; k8 < 64; k8 += 8) {
            uint32_t ah[4];
            ah[0] = tf32_of(Av[(k8 + tig) * 40 + mB + gid]);
            ah[1] = tf32_of(Av[(k8 + tig) * 40 + mB + gid + 8]);
            ah[2] = tf32_of(Av[(k8 + tig + 4) * 40 + mB + gid]);
            ah[3] = tf32_of(Av[(k8 + tig + 4) * 40 + mB + gid + 8]);
#pragma unroll
            for (int nt = 0; nt < 2; nt++) {
                int c = nB + nt * 8 + gid;
                mma1(acc[nt], ah, Bt[(k8 + tig) * 72 + c], Bt[(k8 + 4 + tig) * 72 + c]);
            }
        }
#pragma unroll
        for (int nt = 0; nt < 2; nt++) {
            int lc = lBase + nB + nt * 8 + 2 * tig;
            int m = mB + gid;
            int j = (q0 + m) + lc - (Tc - 1);
            if (j >= 0 && j < Tc) Sb[m * SB_STR + j] += acc[nt][0];
            if (j + 1 >= 0 && j + 1 < Tc) Sb[m * SB_STR + j + 1] += acc[nt][1];
            int j2 = j + 8;
            if (j2 >= 0 && j2 < Tc) Sb[(m + 8) * SB_STR + j2] += acc[nt][2];
            if (j2 + 1 >= 0 && j2 + 1 < Tc) Sb[(m + 8) * SB_STR + j2 + 1] += acc[nt][3];
        }
    }
    __syncthreads();

    // ================= phase 3: softmax (scale 0.125) =================
    {
#pragma unroll
        for (int rr = 0; rr < 4; rr++) {
            float* row = Sb + (w * 4 + rr) * SB_STR;
            float mx = -3.4e38f;
            for (int c = lane; c < Tc; c += 32) mx = fmaxf(mx, row[c]);
#pragma unroll
            for (int o = 16; o; o >>= 1) mx = fmaxf(mx, __shfl_xor_sync(0xffffffffu, mx, o));
            float sum = 0.f;
            for (int c = lane; c < Tc; c += 32) {
                float e = expf(0.125f * (row[c] - mx));
                row[c] = e;
                sum += e;
            }
#pragma unroll
            for (int o = 16; o; o >>= 1) sum += __shfl_xor_sync(0xffffffffu, sum, o);
            float inv = 1.f / sum;
            for (int c = lane; c < Tc; c += 32) row[c] *= inv;
        }
    }
    __syncthreads();

    // ---- write probs (single pass, coalesced) ----
    {
        float* pb = probs + ((size_t)bh << 20) + (size_t)q0 * Tc;
#pragma unroll 4
        for (int r = 0; r < 32; r++) {
            float4 val = *(float4*)&Sb[r * SB_STR + 4 * t];
            *(float4*)(pb + (size_t)r * Tc + 4 * t) = val;
        }
    }

    // ================= phase 4: ctx = probs @ V =================
    float acc2[2][4] = {{0.f, 0.f, 0.f, 0.f}, {0.f, 0.f, 0.f, 0.f}};
    for (int kc = 0; kc < Tc; kc += 64) {
        const float* vp = V + ((size_t)(zb * Tc) + kc + kr) * Dc + h * HSc + dB2;
        float4 r0 = *(const float4*)(vp + 0), r1 = *(const float4*)(vp + 4);
        float4 r2 = *(const float4*)(vp + 8), r3 = *(const float4*)(vp + 12);
        __syncthreads();
        *(float4*)&Bt[kr * 72 + dB2 + 0] = r0;
        *(float4*)&Bt[kr * 72 + dB2 + 4] = r1;
        *(float4*)&Bt[kr * 72 + dB2 + 8] = r2;
        *(float4*)&Bt[kr * 72 + dB2 + 12] = r3;
        __syncthreads();

#pragma unroll
        for (int k8 = 0; k8 < 64; k8 += 8) {
            uint32_t ah[4];
            const float* arow = Sb + (mB + gid) * SB_STR + kc;
            const float* arow8 = arow + 8 * SB_STR;
            ah[0] = tf32_of(arow[k8 + tig]);
            ah[1] = tf32_of(arow8[k8 + tig]);
            ah[2] = tf32_of(arow[k8 + tig + 4]);
            ah[3] = tf32_of(arow8[k8 + tig + 4]);
#pragma unroll
            for (int nt = 0; nt < 2; nt++) {
                int c = nB + nt * 8 + gid;
                mma1(acc2[nt], ah, Bt[(k8 + tig) * 72 + c], Bt[(k8 + 4 + tig) * 72 + c]);
            }
        }
    }
    {
        int r = q0 + mB + gid;
#pragma unroll
        for (int nt = 0; nt < 2; nt++) {
            int c = nB + nt * 8 + 2 * tig;
            *(float2*)(ctx + ((size_t)(zb * Tc) + r) * Dc + h * HSc + c) =
                make_float2(acc2[nt][0], acc2[nt][1]);
            *(float2*)(ctx + ((size_t)(zb * Tc) + r + 8) * Dc + h * HSc + c) =
                make_float2(acc2[nt][2], acc2[nt][3]);
        }
    }
}

// ============================================================
extern "C" void kernel_launch(void* const* d_in, const int* in_sizes, int n_in,
                              void* d_out, int out_size) {
    const float* hs  = (const float*)d_in[0];
    const float* rpe = (const float*)d_in[1];
    const float* Wq  = (const float*)d_in[2];
    const float* bq  = (const float*)d_in[3];
    const float* Wk  = (const float*)d_in[4];
    const float* bk  = (const float*)d_in[5];
    const float* Wv  = (const float*)d_in[6];
    const float* bv  = (const float*)d_in[7];
    const float* Wo  = (const float*)d_in[8];
    const float* bo  = (const float*)d_in[9];
    const float* Wp  = (const float*)d_in[10];
    const float* pu  = (const float*)d_in[11];
    const float* pvb = (const float*)d_in[12];

    float* out = (float*)d_out;                 // (B,T,D)
    float* S   = out + (size_t)Bc * Tc * Dc;    // (B,H,T,T) probs

    float *pq, *pk, *pv, *pp, *pctx;
    cudaGetSymbolAddress((void**)&pq,   g_q);
    cudaGetSymbolAddress((void**)&pk,   g_k);
    cudaGetSymbolAddress((void**)&pv,   g_v);
    cudaGetSymbolAddress((void**)&pp,   g_p);
    cudaGetSymbolAddress((void**)&pctx, g_ctx);

    cudaFuncSetAttribute(fused_attn, cudaFuncAttributeMaxDynamicSharedMemorySize,
                         FUSED_SMEM_BYTES);

    dim3 thr(256);
    gemm_qkv<<<dim3(24, 32), thr>>>(hs, Wq, Wk, Wv, bq, bk, bv, pq, pk, pv);
    gemm_tc_nt<<<dim3(8, 16), thr>>>(rpe, Wp, nullptr, pp, Lc, Dc, Dc);

    fused_attn<<<dim3(Tc / 32, Bc * Hc), thr, FUSED_SMEM_BYTES>>>(
        pq, pk, pp, pv, pu, pvb, S, pctx);

    gemm_tc_nt<<<dim3(8, 32), thr>>>(pctx, Wo, bo, out, Bc * Tc, Dc, Dc);
}

// round 5
// speedup vs baseline: 1.5988x; 1.0014x over previous
#include <cuda_runtime.h>
#include <math.h>
#include <stdint.h>

#define Bc 4
#define Tc 1024
#define Dc 1024
#define Hc 16
#define HSc 64
#define Lc 2047

// -------- scratch (static device globals; no allocations allowed) --------
__device__ float g_q[Bc * Tc * Dc];
__device__ float g_k[Bc * Tc * Dc];
__device__ float g_v[Bc * Tc * Dc];
__device__ float g_p[Lc * Dc];
__device__ float g_ctx[Bc * Tc * Dc];

// ============================================================
// tf32 helpers (plain tf32: single MMA, round-to-nearest)
// ============================================================
__device__ __forceinline__ uint32_t tf32_of(float x) {
    uint32_t r;
    asm("cvt.rna.tf32.f32 %0, %1;" : "=r"(r) : "f"(x));
    return r;
}
__device__ __forceinline__ void mma8(float* d, const uint32_t* a, const uint32_t* b) {
    asm volatile(
        "mma.sync.aligned.m16n8k8.row.col.f32.tf32.tf32.f32 "
        "{%0,%1,%2,%3},{%4,%5,%6,%7},{%8,%9},{%0,%1,%2,%3};"
        : "+f"(d[0]), "+f"(d[1]), "+f"(d[2]), "+f"(d[3])
        : "r"(a[0]), "r"(a[1]), "r"(a[2]), "r"(a[3]), "r"(b[0]), "r"(b[1]));
}
__device__ __forceinline__ void mma1(float* acc, const uint32_t a[4], float b0f, float b1f) {
    uint32_t b[2];
    b[0] = tf32_of(b0f);
    b[1] = tf32_of(b1f);
    mma8(acc, a, b);
}

// ============================================================
// Fused QKV projection: C{q,k,v}[4096,1024] = hs @ W{q,k,v}^T + b
// 128x128 block, BK=16, double buffered. grid (24, 32).
// ============================================================
__global__ __launch_bounds__(256, 2) void gemm_qkv(
    const float* __restrict__ A,
    const float* __restrict__ Wq, const float* __restrict__ Wk, const float* __restrict__ Wv,
    const float* __restrict__ bq, const float* __restrict__ bk, const float* __restrict__ bv,
    float* __restrict__ Cq, float* __restrict__ Ck, float* __restrict__ Cv) {
    __shared__ float As[2][16][136];
    __shared__ float Bs[2][16][136];
    const int tid = threadIdx.x;
    const int sel = blockIdx.x >> 3;
    const float* W = (sel == 0) ? Wq : (sel == 1) ? Wk : Wv;
    const float* bias = (sel == 0) ? bq : (sel == 1) ? bk : bv;
    float* C = (sel == 0) ? Cq : (sel == 1) ? Ck : Cv;
    const int m0 = blockIdx.y * 128, n0 = (blockIdx.x & 7) * 128;
    const int lrow = tid >> 1, lk = (tid & 1) * 8;
    const int lane = tid & 31, wid = tid >> 5;
    const int mBase = (wid >> 1) * 32, nBase = (wid & 1) * 64;
    const int gid = lane >> 2, tig = lane & 3;

    float acc[2][8][4];
#pragma unroll
    for (int i = 0; i < 2; i++)
#pragma unroll
        for (int j = 0; j < 8; j++)
#pragma unroll
            for (int c = 0; c < 4; c++) acc[i][j][c] = 0.f;

    const float* Arow = A + (size_t)(m0 + lrow) * Dc + lk;
    const float* Wrow = W + (size_t)(n0 + lrow) * Dc + lk;

    float4 sa0, sa1, sb0, sb1;
    sa0 = *(const float4*)(Arow + 0);
    sa1 = *(const float4*)(Arow + 4);
    sb0 = *(const float4*)(Wrow + 0);
    sb1 = *(const float4*)(Wrow + 4);
    {
        float* as = &As[0][lk][lrow];
        as[0 * 136] = sa0.x; as[1 * 136] = sa0.y; as[2 * 136] = sa0.z; as[3 * 136] = sa0.w;
        as[4 * 136] = sa1.x; as[5 * 136] = sa1.y; as[6 * 136] = sa1.z; as[7 * 136] = sa1.w;
        float* bs = &Bs[0][lk][lrow];
        bs[0 * 136] = sb0.x; bs[1 * 136] = sb0.y; bs[2 * 136] = sb0.z; bs[3 * 136] = sb0.w;
        bs[4 * 136] = sb1.x; bs[5 * 136] = sb1.y; bs[6 * 136] = sb1.z; bs[7 * 136] = sb1.w;
    }
    __syncthreads();

    const int nk = Dc / 16;
    for (int kt = 0; kt < nk; kt++) {
        const int cur = kt & 1;
        const bool more = (kt + 1) < nk;
        if (more) {
            const float* ap = Arow + (kt + 1) * 16;
            const float* wp = Wrow + (kt + 1) * 16;
            sa0 = *(const float4*)(ap + 0);
            sa1 = *(const float4*)(ap + 4);
            sb0 = *(const float4*)(wp + 0);
            sb1 = *(const float4*)(wp + 4);
        }
        const float* Ac = &As[cur][0][0];
        const float* Bcp = &Bs[cur][0][0];
#pragma unroll
        for (int k8 = 0; k8 < 16; k8 += 8) {
            uint32_t ah[2][4];
#pragma unroll
            for (int mt = 0; mt < 2; mt++) {
                int r0 = mBase + mt * 16 + gid;
                ah[mt][0] = tf32_of(Ac[(k8 + tig) * 136 + r0]);
                ah[mt][1] = tf32_of(Ac[(k8 + tig) * 136 + r0 + 8]);
                ah[mt][2] = tf32_of(Ac[(k8 + tig + 4) * 136 + r0]);
                ah[mt][3] = tf32_of(Ac[(k8 + tig + 4) * 136 + r0 + 8]);
            }
#pragma unroll
            for (int nt = 0; nt < 8; nt++) {
                int c = nBase + nt * 8 + gid;
                uint32_t bh[2];
                bh[0] = tf32_of(Bcp[(k8 + tig) * 136 + c]);
                bh[1] = tf32_of(Bcp[(k8 + 4 + tig) * 136 + c]);
#pragma unroll
                for (int mt = 0; mt < 2; mt++) mma8(acc[mt][nt], ah[mt], bh);
            }
        }
        if (more) {
            const int nb = cur ^ 1;
            float* as = &As[nb][lk][lrow];
            as[0 * 136] = sa0.x; as[1 * 136] = sa0.y; as[2 * 136] = sa0.z; as[3 * 136] = sa0.w;
            as[4 * 136] = sa1.x; as[5 * 136] = sa1.y; as[6 * 136] = sa1.z; as[7 * 136] = sa1.w;
            float* bs = &Bs[nb][lk][lrow];
            bs[0 * 136] = sb0.x; bs[1 * 136] = sb0.y; bs[2 * 136] = sb0.z; bs[3 * 136] = sb0.w;
            bs[4 * 136] = sb1.x; bs[5 * 136] = sb1.y; bs[6 * 136] = sb1.z; bs[7 * 136] = sb1.w;
            __syncthreads();
        }
    }

#pragma unroll
    for (int mt = 0; mt < 2; mt++) {
        int r = m0 + mBase + mt * 16 + gid;
#pragma unroll
        for (int nt = 0; nt < 8; nt++) {
            int c = n0 + nBase + nt * 8 + 2 * tig;
            float b0v = bias[c], b1v = bias[c + 1];
            *(float2*)(C + (size_t)r * Dc + c) =
                make_float2(acc[mt][nt][0] + b0v, acc[mt][nt][1] + b1v);
            *(float2*)(C + (size_t)(r + 8) * Dc + c) =
                make_float2(acc[mt][nt][2] + b0v, acc[mt][nt][3] + b1v);
        }
    }
}

// ============================================================
// Generic C[M,N] = A[M,K] @ W[N,K]^T (+bias).  (pos + out projections)
// ============================================================
__global__ __launch_bounds__(256, 2) void gemm_tc_nt(
    const float* __restrict__ A, const float* __restrict__ W,
    const float* __restrict__ bias, float* __restrict__ C,
    int M, int N, int K) {
    __shared__ float As[2][16][136];
    __shared__ float Bs[2][16][136];
    const int tid = threadIdx.x;
    const int m0 = blockIdx.y * 128, n0 = blockIdx.x * 128;
    const int lrow = tid >> 1, lk = (tid & 1) * 8;
    const int lane = tid & 31, wid = tid >> 5;
    const int mBase = (wid >> 1) * 32, nBase = (wid & 1) * 64;
    const int gid = lane >> 2, tig = lane & 3;

    float acc[2][8][4];
#pragma unroll
    for (int i = 0; i < 2; i++)
#pragma unroll
        for (int j = 0; j < 8; j++)
#pragma unroll
            for (int c = 0; c < 4; c++) acc[i][j][c] = 0.f;

    const bool aval = (m0 + lrow) < M;
    const bool wval = (n0 + lrow) < N;
    const float* Arow = A + (size_t)(m0 + lrow) * K + lk;
    const float* Wrow = W + (size_t)(n0 + lrow) * K + lk;
    const float4 f4z = make_float4(0.f, 0.f, 0.f, 0.f);

    float4 sa0, sa1, sb0, sb1;
    sa0 = aval ? *(const float4*)(Arow + 0) : f4z;
    sa1 = aval ? *(const float4*)(Arow + 4) : f4z;
    sb0 = wval ? *(const float4*)(Wrow + 0) : f4z;
    sb1 = wval ? *(const float4*)(Wrow + 4) : f4z;
    {
        float* as = &As[0][lk][lrow];
        as[0 * 136] = sa0.x; as[1 * 136] = sa0.y; as[2 * 136] = sa0.z; as[3 * 136] = sa0.w;
        as[4 * 136] = sa1.x; as[5 * 136] = sa1.y; as[6 * 136] = sa1.z; as[7 * 136] = sa1.w;
        float* bs = &Bs[0][lk][lrow];
        bs[0 * 136] = sb0.x; bs[1 * 136] = sb0.y; bs[2 * 136] = sb0.z; bs[3 * 136] = sb0.w;
        bs[4 * 136] = sb1.x; bs[5 * 136] = sb1.y; bs[6 * 136] = sb1.z; bs[7 * 136] = sb1.w;
    }
    __syncthreads();

    const int nk = K / 16;
    for (int kt = 0; kt < nk; kt++) {
        const int cur = kt & 1;
        const bool more = (kt + 1) < nk;
        if (more) {
            const float* ap = Arow + (kt + 1) * 16;
            const float* wp = Wrow + (kt + 1) * 16;
            sa0 = aval ? *(const float4*)(ap + 0) : f4z;
            sa1 = aval ? *(const float4*)(ap + 4) : f4z;
            sb0 = wval ? *(const float4*)(wp + 0) : f4z;
            sb1 = wval ? *(const float4*)(wp + 4) : f4z;
        }
        const float* Ac = &As[cur][0][0];
        const float* Bcp = &Bs[cur][0][0];
#pragma unroll
        for (int k8 = 0; k8 < 16; k8 += 8) {
            uint32_t ah[2][4];
#pragma unroll
            for (int mt = 0; mt < 2; mt++) {
                int r0 = mBase + mt * 16 + gid;
                ah[mt][0] = tf32_of(Ac[(k8 + tig) * 136 + r0]);
                ah[mt][1] = tf32_of(Ac[(k8 + tig) * 136 + r0 + 8]);
                ah[mt][2] = tf32_of(Ac[(k8 + tig + 4) * 136 + r0]);
                ah[mt][3] = tf32_of(Ac[(k8 + tig + 4) * 136 + r0 + 8]);
            }
#pragma unroll
            for (int nt = 0; nt < 8; nt++) {
                int c = nBase + nt * 8 + gid;
                uint32_t bh[2];
                bh[0] = tf32_of(Bcp[(k8 + tig) * 136 + c]);
                bh[1] = tf32_of(Bcp[(k8 + 4 + tig) * 136 + c]);
#pragma unroll
                for (int mt = 0; mt < 2; mt++) mma8(acc[mt][nt], ah[mt], bh);
            }
        }
        if (more) {
            const int nb = cur ^ 1;
            float* as = &As[nb][lk][lrow];
            as[0 * 136] = sa0.x; as[1 * 136] = sa0.y; as[2 * 136] = sa0.z; as[3 * 136] = sa0.w;
            as[4 * 136] = sa1.x; as[5 * 136] = sa1.y; as[6 * 136] = sa1.z; as[7 * 136] = sa1.w;
            float* bs = &Bs[nb][lk][lrow];
            bs[0 * 136] = sb0.x; bs[1 * 136] = sb0.y; bs[2 * 136] = sb0.z; bs[3 * 136] = sb0.w;
            bs[4 * 136] = sb1.x; bs[5 * 136] = sb1.y; bs[6 * 136] = sb1.z; bs[7 * 136] = sb1.w;
            __syncthreads();
        }
    }

#pragma unroll
    for (int mt = 0; mt < 2; mt++) {
        int r = m0 + mBase + mt * 16 + gid;
#pragma unroll
        for (int nt = 0; nt < 8; nt++) {
            int c = n0 + nBase + nt * 8 + 2 * tig;
            float b0v = bias ? bias[c] : 0.f;
            float b1v = bias ? bias[c + 1] : 0.f;
            if (r < M)
                *(float2*)(C + (size_t)r * N + c) =
                    make_float2(acc[mt][nt][0] + b0v, acc[mt][nt][1] + b1v);
            if (r + 8 < M)
                *(float2*)(C + (size_t)(r + 8) * N + c) =
                    make_float2(acc[mt][nt][2] + b0v, acc[mt][nt][3] + b1v);
        }
    }
}

// ============================================================
// FUSED attention: per block = (bh, 32 q-rows):
//   Sb[32][1024] = (q+u)K^T ; Sb += band((q+v)P^T) ; softmax(Sb/8) ;
//   probs <- Sb (single gmem write) ; ctx = Sb @ V.
// ============================================================
#define SB_STR 1028
#define SB_FLOATS (32 * SB_STR)
#define AU_OFF SB_FLOATS
#define AV_OFF (AU_OFF + 64 * 40)
#define BT_OFF (AV_OFF + 64 * 40)
#define FUSED_SMEM_BYTES ((BT_OFF + 64 * 72) * 4)

__global__ __launch_bounds__(256, 1) void fused_attn(
    const float* __restrict__ Q, const float* __restrict__ K,
    const float* __restrict__ P, const float* __restrict__ V,
    const float* __restrict__ u, const float* __restrict__ vb,
    float* __restrict__ probs, float* __restrict__ ctx) {
    extern __shared__ float sm[];
    float* Sb = sm;
    float* Au = sm + AU_OFF;
    float* Av = sm + AV_OFF;
    float* Bt = sm + BT_OFF;

    const int t = threadIdx.x;
    const int bh = blockIdx.y, zb = bh >> 4, h = bh & 15;
    const int q0 = blockIdx.x * 32;
    const int lane = t & 31, w = t >> 5;
    const int mB = (w & 1) * 16, nB = (w >> 1) * 16;
    const int gid = lane >> 2, tig = lane & 3;

    // ---- load q tile (32x64), build q+u and q+v transposed [d][m] ----
    {
        int qr = t >> 3;             // 0..31
        int dB = (t & 7) * 8;        // 0..56
        const float* qp = Q + ((size_t)(zb * Tc) + q0 + qr) * Dc + h * HSc + dB;
        float4 a0 = *(const float4*)(qp + 0), a1 = *(const float4*)(qp + 4);
        const float* up = u + h * HSc + dB;
        const float* vp = vb + h * HSc + dB;
        float4 u0 = *(const float4*)(up + 0), u1 = *(const float4*)(up + 4);
        float4 v0 = *(const float4*)(vp + 0), v1 = *(const float4*)(vp + 4);
        Au[(dB + 0) * 40 + qr] = a0.x + u0.x; Av[(dB + 0) * 40 + qr] = a0.x + v0.x;
        Au[(dB + 1) * 40 + qr] = a0.y + u0.y; Av[(dB + 1) * 40 + qr] = a0.y + v0.y;
        Au[(dB + 2) * 40 + qr] = a0.z + u0.z; Av[(dB + 2) * 40 + qr] = a0.z + v0.z;
        Au[(dB + 3) * 40 + qr] = a0.w + u0.w; Av[(dB + 3) * 40 + qr] = a0.w + v0.w;
        Au[(dB + 4) * 40 + qr] = a1.x + u1.x; Av[(dB + 4) * 40 + qr] = a1.x + v1.x;
        Au[(dB + 5) * 40 + qr] = a1.y + u1.y; Av[(dB + 5) * 40 + qr] = a1.y + v1.y;
        Au[(dB + 6) * 40 + qr] = a1.z + u1.z; Av[(dB + 6) * 40 + qr] = a1.z + v1.z;
        Au[(dB + 7) * 40 + qr] = a1.w + u1.w; Av[(dB + 7) * 40 + qr] = a1.w + v1.w;
    }

    const int kr = t >> 2;           // 0..63
    const int dB2 = (t & 3) * 16;    // 0..48

    // ================= phase 1: ac = (q+u) K^T  =================
    for (int j0 = 0; j0 < Tc; j0 += 64) {
        const float* kp = K + ((size_t)(zb * Tc) + j0 + kr) * Dc + h * HSc + dB2;
        float4 r0 = *(const float4*)(kp + 0), r1 = *(const float4*)(kp + 4);
        float4 r2 = *(const float4*)(kp + 8), r3 = *(const float4*)(kp + 12);
        __syncthreads();
        Bt[(dB2 + 0) * 72 + kr] = r0.x; Bt[(dB2 + 1) * 72 + kr] = r0.y;
        Bt[(dB2 + 2) * 72 + kr] = r0.z; Bt[(dB2 + 3) * 72 + kr] = r0.w;
        Bt[(dB2 + 4) * 72 + kr] = r1.x; Bt[(dB2 + 5) * 72 + kr] = r1.y;
        Bt[(dB2 + 6) * 72 + kr] = r1.z; Bt[(dB2 + 7) * 72 + kr] = r1.w;
        Bt[(dB2 + 8) * 72 + kr] = r2.x; Bt[(dB2 + 9) * 72 + kr] = r2.y;
        Bt[(dB2 + 10) * 72 + kr] = r2.z; Bt[(dB2 + 11) * 72 + kr] = r2.w;
        Bt[(dB2 + 12) * 72 + kr] = r3.x; Bt[(dB2 + 13) * 72 + kr] = r3.y;
        Bt[(dB2 + 14) * 72 + kr] = r3.z; Bt[(dB2 + 15) * 72 + kr] = r3.w;
        __syncthreads();

        float acc[2][4] = {{0.f, 0.f, 0.f, 0.f}, {0.f, 0.f, 0.f, 0.f}};
#pragma unroll
        for (int k8 = 0; k8 < 64; k8 += 8) {
            uint32_t ah[4];
            ah[0] = tf32_of(Au[(k8 + tig) * 40 + mB + gid]);
            ah[1] = tf32_of(Au[(k8 + tig) * 40 + mB + gid + 8]);
            ah[2] = tf32_of(Au[(k8 + tig + 4) * 40 + mB + gid]);
            ah[3] = tf32_of(Au[(k8 + tig + 4) * 40 + mB + gid + 8]);
#pragma unroll
            for (int nt = 0; nt < 2; nt++) {
                int c = nB + nt * 8 + gid;
                mma1(acc[nt], ah, Bt[(k8 + tig) * 72 + c], Bt[(k8 + 4 + tig) * 72 + c]);
            }
        }
#pragma unroll
        for (int nt = 0; nt < 2; nt++) {
            int col = j0 + nB + nt * 8 + 2 * tig;
            *(float2*)&Sb[(mB + gid) * SB_STR + col] = make_float2(acc[nt][0], acc[nt][1]);
            *(float2*)&Sb[(mB + gid + 8) * SB_STR + col] = make_float2(acc[nt][2], acc[nt][3]);
        }
    }

    // ================= phase 2: bd band, scatter-add =================
    const int lStart = (Tc - 1) - (q0 + 31);   // >= 0
    for (int it = 0; it < 17; it++) {
        int lBase = lStart + it * 64;
        int l = lBase + kr;
        float4 r0, r1, r2, r3;
        if (l < Lc) {
            const float* pp = P + (size_t)l * Dc + h * HSc + dB2;
            r0 = *(const float4*)(pp + 0); r1 = *(const float4*)(pp + 4);
            r2 = *(const float4*)(pp + 8); r3 = *(const float4*)(pp + 12);
        } else {
            r0 = r1 = r2 = r3 = make_float4(0.f, 0.f, 0.f, 0.f);
        }
        __syncthreads();
        Bt[(dB2 + 0) * 72 + kr] = r0.x; Bt[(dB2 + 1) * 72 + kr] = r0.y;
        Bt[(dB2 + 2) * 72 + kr] = r0.z; Bt[(dB2 + 3) * 72 + kr] = r0.w;
        Bt[(dB2 + 4) * 72 + kr] = r1.x; Bt[(dB2 + 5) * 72 + kr] = r1.y;
        Bt[(dB2 + 6) * 72 + kr] = r1.z; Bt[(dB2 + 7) * 72 + kr] = r1.w;
        Bt[(dB2 + 8) * 72 + kr] = r2.x; Bt[(dB2 + 9) * 72 + kr] = r2.y;
        Bt[(dB2 + 10) * 72 + kr] = r2.z; Bt[(dB2 + 11) * 72 + kr] = r2.w;
        Bt[(dB2 + 12) * 72 + kr] = r3.x; Bt[(dB2 + 13) * 72 + kr] = r3.y;
        Bt[(dB2 + 14) * 72 + kr] = r3.z; Bt[(dB2 + 15) * 72 + kr] = r3.w;
        __syncthreads();

        float acc[2][4] = {{0.f, 0.f, 0.f, 0.f}, {0.f, 0.f, 0.f, 0.f}};
#pragma unroll
        for (int k8 = 0; k8 < 64; k8 += 8) {
            uint32_t ah[4];
            ah[0] = tf32_of(Av[(k8 + tig) * 40 + mB + gid]);
            ah[1] = tf32_of(Av[(k8 + tig) * 40 + mB + gid + 8]);
            ah[2] = tf32_of(Av[(k8 + tig + 4) * 40 + mB + gid]);
            ah[3] = tf32_of(Av[(k8 + tig + 4) * 40 + mB + gid + 8]);
#pragma unroll
            for (int nt = 0; nt < 2; nt++) {
                int c = nB + nt * 8 + gid;
                mma1(acc[nt], ah, Bt[(k8 + tig) * 72 + c], Bt[(k8 + 4 + tig) * 72 + c]);
            }
        }
#pragma unroll
        for (int nt = 0; nt < 2; nt++) {
            int lc = lBase + nB + nt * 8 + 2 * tig;
            int m = mB + gid;
            int j = (q0 + m) + lc - (Tc - 1);
            if (j >= 0 && j < Tc) Sb[m * SB_STR + j] += acc[nt][0];
            if (j + 1 >= 0 && j + 1 < Tc) Sb[m * SB_STR + j + 1] += acc[nt][1];
            int j2 = j + 8;
            if (j2 >= 0 && j2 < Tc) Sb[(m + 8) * SB_STR + j2] += acc[nt][2];
            if (j2 + 1 >= 0 && j2 + 1 < Tc) Sb[(m + 8) * SB_STR + j2 + 1] += acc[nt][3];
        }
    }
    __syncthreads();

    // ================= phase 3: softmax (scale 0.125) =================
    {
#pragma unroll
        for (int rr = 0; rr < 4; rr++) {
            float* row = Sb + (w * 4 + rr) * SB_STR;
            float mx = -3.4e38f;
            for (int c = lane; c < Tc; c += 32) mx = fmaxf(mx, row[c]);
#pragma unroll
            for (int o = 16; o; o >>= 1) mx = fmaxf(mx, __shfl_xor_sync(0xffffffffu, mx, o));
            float sum = 0.f;
            for (int c = lane; c < Tc; c += 32) {
                float e = expf(0.125f * (row[c] - mx));
                row[c] = e;
                sum += e;
            }
#pragma unroll
            for (int o = 16; o; o >>= 1) sum += __shfl_xor_sync(0xffffffffu, sum, o);
            float inv = 1.f / sum;
            for (int c = lane; c < Tc; c += 32) row[c] *= inv;
        }
    }
    __syncthreads();

    // ---- write probs (single pass, coalesced) ----
    {
        float* pb = probs + ((size_t)bh << 20) + (size_t)q0 * Tc;
#pragma unroll 4
        for (int r = 0; r < 32; r++) {
            float4 val = *(float4*)&Sb[r * SB_STR + 4 * t];
            *(float4*)(pb + (size_t)r * Tc + 4 * t) = val;
        }
    }

    // ================= phase 4: ctx = probs @ V =================
    float acc2[2][4] = {{0.f, 0.f, 0.f, 0.f}, {0.f, 0.f, 0.f, 0.f}};
    for (int kc = 0; kc < Tc; kc += 64) {
        const float* vp = V + ((size_t)(zb * Tc) + kc + kr) * Dc + h * HSc + dB2;
        float4 r0 = *(const float4*)(vp + 0), r1 = *(const float4*)(vp + 4);
        float4 r2 = *(const float4*)(vp + 8), r3 = *(const float4*)(vp + 12);
        __syncthreads();
        *(float4*)&Bt[kr * 72 + dB2 + 0] = r0;
        *(float4*)&Bt[kr * 72 + dB2 + 4] = r1;
        *(float4*)&Bt[kr * 72 + dB2 + 8] = r2;
        *(float4*)&Bt[kr * 72 + dB2 + 12] = r3;
        __syncthreads();

#pragma unroll
        for (int k8 = 0; k8 < 64; k8 += 8) {
            uint32_t ah[4];
            const float* arow = Sb + (mB + gid) * SB_STR + kc;
            const float* arow8 = arow + 8 * SB_STR;
            ah[0] = tf32_of(arow[k8 + tig]);
            ah[1] = tf32_of(arow8[k8 + tig]);
            ah[2] = tf32_of(arow[k8 + tig + 4]);
            ah[3] = tf32_of(arow8[k8 + tig + 4]);
#pragma unroll
            for (int nt = 0; nt < 2; nt++) {
                int c = nB + nt * 8 + gid;
                mma1(acc2[nt], ah, Bt[(k8 + tig) * 72 + c], Bt[(k8 + 4 + tig) * 72 + c]);
            }
        }
    }
    {
        int r = q0 + mB + gid;
#pragma unroll
        for (int nt = 0; nt < 2; nt++) {
            int c = nB + nt * 8 + 2 * tig;
            *(float2*)(ctx + ((size_t)(zb * Tc) + r) * Dc + h * HSc + c) =
                make_float2(acc2[nt][0], acc2[nt][1]);
            *(float2*)(ctx + ((size_t)(zb * Tc) + r + 8) * Dc + h * HSc + c) =
                make_float2(acc2[nt][2], acc2[nt][3]);
        }
    }
}

// ============================================================
extern "C" void kernel_launch(void* const* d_in, const int* in_sizes, int n_in,
                              void* d_out, int out_size) {
    const float* hs  = (const float*)d_in[0];
    const float* rpe = (const float*)d_in[1];
    const float* Wq  = (const float*)d_in[2];
    const float* bq  = (const float*)d_in[3];
    const float* Wk  = (const float*)d_in[4];
    const float* bk  = (const float*)d_in[5];
    const float* Wv  = (const float*)d_in[6];
    const float* bv  = (const float*)d_in[7];
    const float* Wo  = (const float*)d_in[8];
    const float* bo  = (const float*)d_in[9];
    const float* Wp  = (const float*)d_in[10];
    const float* pu  = (const float*)d_in[11];
    const float* pvb = (const float*)d_in[12];

    float* out = (float*)d_out;                 // (B,T,D)
    float* S   = out + (size_t)Bc * Tc * Dc;    // (B,H,T,T) probs

    float *pq, *pk, *pv, *pp, *pctx;
    cudaGetSymbolAddress((void**)&pq,   g_q);
    cudaGetSymbolAddress((void**)&pk,   g_k);
    cudaGetSymbolAddress((void**)&pv,   g_v);
    cudaGetSymbolAddress((void**)&pp,   g_p);
    cudaGetSymbolAddress((void**)&pctx, g_ctx);

    cudaFuncSetAttribute(fused_attn, cudaFuncAttributeMaxDynamicSharedMemorySize,
                         FUSED_SMEM_BYTES);

    dim3 thr(256);
    gemm_qkv<<<dim3(24, 32), thr>>>(hs, Wq, Wk, Wv, bq, bk, bv, pq, pk, pv);
    gemm_tc_nt<<<dim3(8, 16), thr>>>(rpe, Wp, nullptr, pp, Lc, Dc, Dc);

    fused_attn<<<dim3(Tc / 32, Bc * Hc), thr, FUSED_SMEM_BYTES>>>(
        pq, pk, pp, pv, pu, pvb, S, pctx);

    gemm_tc_nt<<<dim3(8, 32), thr>>>(pctx, Wo, bo, out, Bc * Tc, Dc, Dc);
}

// round 7
// speedup vs baseline: 1.6820x; 1.0521x over previous
#include <cuda_runtime.h>
#include <math.h>
#include <stdint.h>

#define Bc 4
#define Tc 1024
#define Dc 1024
#define Hc 16
#define HSc 64
#define Lc 2047

__device__ float g_q[Bc * Tc * Dc];
__device__ float g_k[Bc * Tc * Dc];
__device__ float g_v[Bc * Tc * Dc];
__device__ float g_p[Lc * Dc];
__device__ float g_ctx[Bc * Tc * Dc];

__device__ __forceinline__ uint32_t tf32_of(float x) {
    uint32_t r;
    asm("cvt.rna.tf32.f32 %0, %1;" : "=r"(r) : "f"(x));
    return r;
}
__device__ __forceinline__ void mma_p(float* d, uint4 a, uint2 b) {
    asm volatile(
        "mma.sync.aligned.m16n8k8.row.col.f32.tf32.tf32.f32 "
        "{%0,%1,%2,%3},{%4,%5,%6,%7},{%8,%9},{%0,%1,%2,%3};"
        : "+f"(d[0]), "+f"(d[1]), "+f"(d[2]), "+f"(d[3])
        : "r"(a.x), "r"(a.y), "r"(a.z), "r"(a.w), "r"(b.x), "r"(b.y));
}

// ---- packed A fragments: per-oct block = RB*128+8 u32 ----
// slot (oct, rb, g, p) u32s [4p..4p+3] = {A[rb16+g][k], A[rb16+8+g][k],
//   A[rb16+g][k+4], A[rb16+8+g][k+4]} with k = oct*8 + (p ^ (g&3)).
template <int RB>
__device__ __forceinline__ void storeA(uint32_t* sA, int oct, int r, const float* f) {
    uint32_t* b = sA + oct * (RB * 128 + 8) + (r >> 4) * 128 + (r & 7) * 16 + ((r >> 3) & 1);
    int gs = r & 3;
#pragma unroll
    for (int p = 0; p < 4; p++) {
        int tq = p ^ gs;
        b[p * 4] = tf32_of(f[tq]);
        b[p * 4 + 2] = tf32_of(f[tq + 4]);
    }
}
template <int RB>
__device__ __forceinline__ uint4 loadA(const uint32_t* sA, int oct, int rb, int gid, int tig) {
    return *(const uint4*)(sA + oct * (RB * 128 + 8) + rb * 128 + gid * 16 +
                           ((tig ^ (gid & 3)) << 2));
}
// ---- packed B fragments: per-oct block = 8*S+8 u32, S = stride in uint2 units ----
template <int S>
__device__ __forceinline__ void storeB(uint32_t* sB, int oct, int c, const float* f) {
    uint32_t* b = sB + oct * (S * 8 + 8) + c * 2;
#pragma unroll
    for (int tq = 0; tq < 4; tq++)
        *(uint2*)(b + tq * S * 2) = make_uint2(tf32_of(f[tq]), tf32_of(f[tq + 4]));
}
template <int S>
__device__ __forceinline__ uint2 loadB(const uint32_t* sB, int oct, int tig, int c) {
    return *(const uint2*)(sB + oct * (S * 8 + 8) + (tig * S + c) * 2);
}

__device__ __forceinline__ void ld8(const float* p, bool ok, float* f) {
    float4 z = make_float4(0.f, 0.f, 0.f, 0.f);
    float4 x0 = ok ? *(const float4*)p : z;
    float4 x1 = ok ? *(const float4*)(p + 4) : z;
    f[0] = x0.x; f[1] = x0.y; f[2] = x0.z; f[3] = x0.w;
    f[4] = x1.x; f[5] = x1.y; f[6] = x1.z; f[7] = x1.w;
}

// ============================================================
// GEMM body: C[M,N] = A @ W^T (+bias). 128x128, BK=16, packed tf32.
// ============================================================
__device__ __forceinline__ void gemm_body(const float* __restrict__ A,
                                          const float* __restrict__ W,
                                          const float* __restrict__ bias,
                                          float* __restrict__ C,
                                          int M, int N, int K, int m0, int n0) {
    __shared__ __align__(16) uint32_t sA[2][2 * (8 * 128 + 8)];
    __shared__ __align__(16) uint32_t sB[2][2 * (132 * 8 + 8)];
    const int tid = threadIdx.x;
    const int lrow = tid >> 1, oct = tid & 1, lk = oct * 8;
    const int lane = tid & 31, wid = tid >> 5;
    const int rb0 = (wid >> 1) * 2, nB = (wid & 1) * 64;
    const int gid = lane >> 2, tig = lane & 3;

    float acc[2][8][4];
#pragma unroll
    for (int i = 0; i < 2; i++)
#pragma unroll
        for (int j = 0; j < 8; j++)
#pragma unroll
            for (int c = 0; c < 4; c++) acc[i][j][c] = 0.f;

    const bool av = (m0 + lrow) < M, wv = (n0 + lrow) < N;
    const float* Ar = A + (size_t)(m0 + lrow) * K + lk;
    const float* Wr = W + (size_t)(n0 + lrow) * K + lk;
    float fA[8], fB[8];
    ld8(Ar, av, fA);
    ld8(Wr, wv, fB);
    storeA<8>(sA[0], oct, lrow, fA);
    storeB<132>(sB[0], oct, lrow, fB);
    __syncthreads();

    const int nk = K / 16;
    for (int kt = 0; kt < nk; kt++) {
        const int cur = kt & 1;
        const bool more = (kt + 1) < nk;
        if (more) {
            ld8(Ar + (kt + 1) * 16, av, fA);
            ld8(Wr + (kt + 1) * 16, wv, fB);
        }
#pragma unroll
        for (int o = 0; o < 2; o++) {
            uint4 a0 = loadA<8>(sA[cur], o, rb0, gid, tig);
            uint4 a1 = loadA<8>(sA[cur], o, rb0 + 1, gid, tig);
#pragma unroll
            for (int nt = 0; nt < 8; nt++) {
                uint2 bv = loadB<132>(sB[cur], o, tig, nB + nt * 8 + gid);
                mma_p(acc[0][nt], a0, bv);
                mma_p(acc[1][nt], a1, bv);
            }
        }
        if (more) {
            storeA<8>(sA[cur ^ 1], oct, lrow, fA);
            storeB<132>(sB[cur ^ 1], oct, lrow, fB);
            __syncthreads();
        }
    }

#pragma unroll
    for (int mt = 0; mt < 2; mt++) {
        int r = m0 + (rb0 + mt) * 16 + gid;
#pragma unroll
        for (int nt = 0; nt < 8; nt++) {
            int c = n0 + nB + nt * 8 + 2 * tig;
            float b0v = bias ? bias[c] : 0.f;
            float b1v = bias ? bias[c + 1] : 0.f;
            if (r < M)
                *(float2*)(C + (size_t)r * N + c) =
                    make_float2(acc[mt][nt][0] + b0v, acc[mt][nt][1] + b1v);
            if (r + 8 < M)
                *(float2*)(C + (size_t)(r + 8) * N + c) =
                    make_float2(acc[mt][nt][2] + b0v, acc[mt][nt][3] + b1v);
        }
    }
}

__global__ __launch_bounds__(256, 2) void gemm_tc_nt(
    const float* __restrict__ A, const float* __restrict__ W,
    const float* __restrict__ bias, float* __restrict__ C, int M, int N, int K) {
    gemm_body(A, W, bias, C, M, N, K, blockIdx.y * 128, blockIdx.x * 128);
}

__global__ __launch_bounds__(256, 2) void gemm_qkv(
    const float* __restrict__ A,
    const float* __restrict__ Wq, const float* __restrict__ Wk, const float* __restrict__ Wv,
    const float* __restrict__ bq, const float* __restrict__ bk, const float* __restrict__ bv,
    float* __restrict__ Cq, float* __restrict__ Ck, float* __restrict__ Cv) {
    const int sel = blockIdx.x >> 3;
    const float* W = (sel == 0) ? Wq : (sel == 1) ? Wk : Wv;
    const float* bias = (sel == 0) ? bq : (sel == 1) ? bk : bv;
    float* C = (sel == 0) ? Cq : (sel == 1) ? Ck : Cv;
    gemm_body(A, W, bias, C, Bc * Tc, Dc, Dc, blockIdx.y * 128, (blockIdx.x & 7) * 128);
}

// ============================================================
// FUSED attention per (bh, 32-row q tile)
// smem (u32): Sb 32*1028 | Au 8*264 | Av 8*264 | Bf 2*8*552
// ============================================================
#define SB_STR 1028
#define AU_OFF (32 * SB_STR)
#define AV_OFF (AU_OFF + 8 * 264)
#define BF0_OFF (AV_OFF + 8 * 264)
#define BF1_OFF (BF0_OFF + 8 * 552)
#define FUSED_SMEM_BYTES ((BF1_OFF + 8 * 552) * 4)

__global__ __launch_bounds__(256, 1) void fused_attn(
    const float* __restrict__ Q, const float* __restrict__ K,
    const float* __restrict__ P, const float* __restrict__ V,
    const float* __restrict__ u, const float* __restrict__ vb,
    float* __restrict__ probs, float* __restrict__ ctx) {
    extern __shared__ __align__(16) uint32_t su[];
    float* Sb = (float*)su;
    uint32_t* Au = su + AU_OFF;
    uint32_t* Av = su + AV_OFF;
    uint32_t* Bf0 = su + BF0_OFF;

    const int t = threadIdx.x;
    const int bh = blockIdx.y, zb = bh >> 4, h = bh & 15;
    const int q0 = blockIdx.x * 32;
    const int lane = t & 31, w = t >> 5;
    const int mB = (w & 1) * 16, rbw = w & 1, nBf = (w >> 1) * 16;
    const int gid = lane >> 2, tig = lane & 3;

    // ---- stage q+u / q+v as packed A fragments (once) ----
    {
        int qr = t >> 3, o = t & 7;
        const float* qp = Q + ((size_t)(zb * Tc) + q0 + qr) * Dc + h * HSc + o * 8;
        const float* up = u + h * HSc + o * 8;
        const float* vp = vb + h * HSc + o * 8;
        float a[8], uu[8], fv[8];
        ld8(qp, true, a);
        ld8(up, true, uu);
        ld8(vp, true, fv);
        float fu2[8], fv2[8];
#pragma unroll
        for (int i = 0; i < 8; i++) { fu2[i] = a[i] + uu[i]; fv2[i] = a[i] + fv[i]; }
        storeA<2>(Au, o, qr, fu2);
        storeA<2>(Av, o, qr, fv2);
    }

    const int kr = t >> 2, qq = t & 3;

    // ================= phase 1: ac = (q+u) K^T =================
    for (int j0 = 0; j0 < Tc; j0 += 64) {
        const float* kp = K + ((size_t)(zb * Tc) + j0 + kr) * Dc + h * HSc + qq * 16;
        float f0[8], f1[8];
        ld8(kp, true, f0);
        ld8(kp + 8, true, f1);
        __syncthreads();
        storeB<68>(Bf0, 2 * qq, kr, f0);
        storeB<68>(Bf0, 2 * qq + 1, kr, f1);
        __syncthreads();

        float acc[2][4] = {{0.f, 0.f, 0.f, 0.f}, {0.f, 0.f, 0.f, 0.f}};
#pragma unroll
        for (int o = 0; o < 8; o++) {
            uint4 a = loadA<2>(Au, o, rbw, gid, tig);
#pragma unroll
            for (int nt = 0; nt < 2; nt++)
                mma_p(acc[nt], a, loadB<68>(Bf0, o, tig, nBf + nt * 8 + gid));
        }
#pragma unroll
        for (int nt = 0; nt < 2; nt++) {
            int col = j0 + nBf + nt * 8 + 2 * tig;
            *(float2*)&Sb[(mB + gid) * SB_STR + col] = make_float2(acc[nt][0], acc[nt][1]);
            *(float2*)&Sb[(mB + gid + 8) * SB_STR + col] = make_float2(acc[nt][2], acc[nt][3]);
        }
    }

    // ================= phase 2: bd band, scatter-add =================
    const int lStart = (Tc - 1) - (q0 + 31);
    for (int it = 0; it < 17; it++) {
        int lBase = lStart + it * 64;
        int l = lBase + kr;
        float f0[8], f1[8];
        if (l < Lc) {
            const float* pp = P + (size_t)l * Dc + h * HSc + qq * 16;
            ld8(pp, true, f0);
            ld8(pp + 8, true, f1);
        } else {
#pragma unroll
            for (int i = 0; i < 8; i++) { f0[i] = 0.f; f1[i] = 0.f; }
        }
        __syncthreads();
        storeB<68>(Bf0, 2 * qq, kr, f0);
        storeB<68>(Bf0, 2 * qq + 1, kr, f1);
        __syncthreads();

        float acc[2][4] = {{0.f, 0.f, 0.f, 0.f}, {0.f, 0.f, 0.f, 0.f}};
#pragma unroll
        for (int o = 0; o < 8; o++) {
            uint4 a = loadA<2>(Av, o, rbw, gid, tig);
#pragma unroll
            for (int nt = 0; nt < 2; nt++)
                mma_p(acc[nt], a, loadB<68>(Bf0, o, tig, nBf + nt * 8 + gid));
        }
#pragma unroll
        for (int nt = 0; nt < 2; nt++) {
            int lc = lBase + nBf + nt * 8 + 2 * tig;
            int m = mB + gid;
            int j = (q0 + m) + lc - (Tc - 1);
            if (j >= 0 && j < Tc) Sb[m * SB_STR + j] += acc[nt][0];
            if (j + 1 >= 0 && j + 1 < Tc) Sb[m * SB_STR + j + 1] += acc[nt][1];
            int j2 = j + 8;
            if (j2 >= 0 && j2 < Tc) Sb[(m + 8) * SB_STR + j2] += acc[nt][2];
            if (j2 + 1 >= 0 && j2 + 1 < Tc) Sb[(m + 8) * SB_STR + j2 + 1] += acc[nt][3];
        }
    }
    __syncthreads();

    // ================= phase 3: softmax (scale 0.125) =================
#pragma unroll
    for (int rr = 0; rr < 4; rr++) {
        float* row = Sb + (w * 4 + rr) * SB_STR;
        float mx = -3.4e38f;
        for (int c = lane; c < Tc; c += 32) mx = fmaxf(mx, row[c]);
#pragma unroll
        for (int o = 16; o; o >>= 1) mx = fmaxf(mx, __shfl_xor_sync(0xffffffffu, mx, o));
        float sum = 0.f;
        for (int c = lane; c < Tc; c += 32) {
            float e = expf(0.125f * (row[c] - mx));
            row[c] = e;
            sum += e;
        }
#pragma unroll
        for (int o = 16; o; o >>= 1) sum += __shfl_xor_sync(0xffffffffu, sum, o);
        float inv = 1.f / sum;
        for (int c = lane; c < Tc; c += 32) row[c] *= inv;
    }
    __syncthreads();

    // ---- write probs ----
    {
        float* pb = probs + ((size_t)bh << 20) + (size_t)q0 * Tc;
#pragma unroll 4
        for (int r = 0; r < 32; r++)
            *(float4*)(pb + (size_t)r * Tc + 4 * t) = *(float4*)&Sb[r * SB_STR + 4 * t];
    }

    // ================= phase 4: ctx = Sb @ V =================
    // V staged pre-converted to tf32 in plain [row][72] u32 layout.
    uint32_t* Vt = Bf0;  // 64*72 = 4608 u32 (fits in the 8832-u32 Bf region)
    float acc2[2][4] = {{0.f, 0.f, 0.f, 0.f}, {0.f, 0.f, 0.f, 0.f}};
    for (int kc = 0; kc < Tc; kc += 64) {
        const float* vp = V + ((size_t)(zb * Tc) + kc + kr) * Dc + h * HSc + qq * 16;
        float f[16];
        ld8(vp, true, f);
        ld8(vp + 8, true, f + 8);
        __syncthreads();
        uint32_t* dst = Vt + kr * 72 + qq * 16;
        *(uint4*)(dst + 0)  = make_uint4(tf32_of(f[0]),  tf32_of(f[1]),  tf32_of(f[2]),  tf32_of(f[3]));
        *(uint4*)(dst + 4)  = make_uint4(tf32_of(f[4]),  tf32_of(f[5]),  tf32_of(f[6]),  tf32_of(f[7]));
        *(uint4*)(dst + 8)  = make_uint4(tf32_of(f[8]),  tf32_of(f[9]),  tf32_of(f[10]), tf32_of(f[11]));
        *(uint4*)(dst + 12) = make_uint4(tf32_of(f[12]), tf32_of(f[13]), tf32_of(f[14]), tf32_of(f[15]));
        __syncthreads();

        const float* ar0 = Sb + (mB + gid) * SB_STR + kc;
        const float* ar8 = ar0 + 8 * SB_STR;
#pragma unroll
        for (int o = 0; o < 8; o++) {
            uint4 a;
            a.x = tf32_of(ar0[o * 8 + tig]);
            a.y = tf32_of(ar8[o * 8 + tig]);
            a.z = tf32_of(ar0[o * 8 + tig + 4]);
            a.w = tf32_of(ar8[o * 8 + tig + 4]);
#pragma unroll
            for (int nt = 0; nt < 2; nt++) {
                int c = nBf + nt * 8 + gid;
                uint2 b;
                b.x = Vt[(o * 8 + tig) * 72 + c];
                b.y = Vt[(o * 8 + tig + 4) * 72 + c];
                mma_p(acc2[nt], a, b);
            }
        }
    }
    {
        int r = q0 + mB + gid;
#pragma unroll
        for (int nt = 0; nt < 2; nt++) {
            int c = nBf + nt * 8 + 2 * tig;
            *(float2*)(ctx + ((size_t)(zb * Tc) + r) * Dc + h * HSc + c) =
                make_float2(acc2[nt][0], acc2[nt][1]);
            *(float2*)(ctx + ((size_t)(zb * Tc) + r + 8) * Dc + h * HSc + c) =
                make_float2(acc2[nt][2], acc2[nt][3]);
        }
    }
}

// ============================================================
extern "C" void kernel_launch(void* const* d_in, const int* in_sizes, int n_in,
                              void* d_out, int out_size) {
    const float* hs  = (const float*)d_in[0];
    const float* rpe = (const float*)d_in[1];
    const float* Wq  = (const float*)d_in[2];
    const float* bq  = (const float*)d_in[3];
    const float* Wk  = (const float*)d_in[4];
    const float* bk  = (const float*)d_in[5];
    const float* Wv  = (const float*)d_in[6];
    const float* bv  = (const float*)d_in[7];
    const float* Wo  = (const float*)d_in[8];
    const float* bo  = (const float*)d_in[9];
    const float* Wp  = (const float*)d_in[10];
    const float* pu  = (const float*)d_in[11];
    const float* pvb = (const float*)d_in[12];

    float* out = (float*)d_out;
    float* S   = out + (size_t)Bc * Tc * Dc;

    float *pq, *pk, *pv, *pp, *pctx;
    cudaGetSymbolAddress((void**)&pq,   g_q);
    cudaGetSymbolAddress((void**)&pk,   g_k);
    cudaGetSymbolAddress((void**)&pv,   g_v);
    cudaGetSymbolAddress((void**)&pp,   g_p);
    cudaGetSymbolAddress((void**)&pctx, g_ctx);

    cudaFuncSetAttribute(fused_attn, cudaFuncAttributeMaxDynamicSharedMemorySize,
                         FUSED_SMEM_BYTES);

    dim3 thr(256);
    gemm_qkv<<<dim3(24, 32), thr>>>(hs, Wq, Wk, Wv, bq, bk, bv, pq, pk, pv);
    gemm_tc_nt<<<dim3(8, 16), thr>>>(rpe, Wp, nullptr, pp, Lc, Dc, Dc);

    fused_attn<<<dim3(Tc / 32, Bc * Hc), thr, FUSED_SMEM_BYTES>>>(
        pq, pk, pp, pv, pu, pvb, S, pctx);

    gemm_tc_nt<<<dim3(8, 32), thr>>>(pctx, Wo, bo, out, Bc * Tc, Dc, Dc);
}

// round 8
// speedup vs baseline: 1.9941x; 1.1855x over previous
#include <cuda_runtime.h>
#include <math.h>
#include <stdint.h>

#define Bc 4
#define Tc 1024
#define Dc 1024
#define Hc 16
#define HSc 64
#define Lc 2047

__device__ float g_q[Bc * Tc * Dc];
__device__ float g_k[Bc * Tc * Dc];
__device__ float g_v[Bc * Tc * Dc];
__device__ float g_p[Lc * Dc];
__device__ float g_ctx[Bc * Tc * Dc];

__device__ __forceinline__ uint32_t tf32_of(float x) {
    uint32_t r;
    asm("cvt.rna.tf32.f32 %0, %1;" : "=r"(r) : "f"(x));
    return r;
}
__device__ __forceinline__ void mma_p(float* d, uint4 a, uint2 b) {
    asm volatile(
        "mma.sync.aligned.m16n8k8.row.col.f32.tf32.tf32.f32 "
        "{%0,%1,%2,%3},{%4,%5,%6,%7},{%8,%9},{%0,%1,%2,%3};"
        : "+f"(d[0]), "+f"(d[1]), "+f"(d[2]), "+f"(d[3])
        : "r"(a.x), "r"(a.y), "r"(a.z), "r"(a.w), "r"(b.x), "r"(b.y));
}

// ---- packed A fragments: per-oct block = RB*128+8 u32 ----
template <int RB>
__device__ __forceinline__ void storeA(uint32_t* sA, int oct, int r, const float* f) {
    uint32_t* b = sA + oct * (RB * 128 + 8) + (r >> 4) * 128 + (r & 7) * 16 + ((r >> 3) & 1);
    int gs = r & 3;
#pragma unroll
    for (int p = 0; p < 4; p++) {
        int tq = p ^ gs;
        b[p * 4] = tf32_of(f[tq]);
        b[p * 4 + 2] = tf32_of(f[tq + 4]);
    }
}
template <int RB>
__device__ __forceinline__ uint4 loadA(const uint32_t* sA, int oct, int rb, int gid, int tig) {
    return *(const uint4*)(sA + oct * (RB * 128 + 8) + rb * 128 + gid * 16 +
                           ((tig ^ (gid & 3)) << 2));
}
// ---- packed B fragments: per-oct block = 8*S+8 u32, S = stride in uint2 units ----
template <int S>
__device__ __forceinline__ void storeB(uint32_t* sB, int oct, int c, const float* f) {
    uint32_t* b = sB + oct * (S * 8 + 8) + c * 2;
#pragma unroll
    for (int tq = 0; tq < 4; tq++)
        *(uint2*)(b + tq * S * 2) = make_uint2(tf32_of(f[tq]), tf32_of(f[tq + 4]));
}
template <int S>
__device__ __forceinline__ uint2 loadB(const uint32_t* sB, int oct, int tig, int c) {
    return *(const uint2*)(sB + oct * (S * 8 + 8) + (tig * S + c) * 2);
}

__device__ __forceinline__ void ld8(const float* p, bool ok, float* f) {
    float4 z = make_float4(0.f, 0.f, 0.f, 0.f);
    float4 x0 = ok ? *(const float4*)p : z;
    float4 x1 = ok ? *(const float4*)(p + 4) : z;
    f[0] = x0.x; f[1] = x0.y; f[2] = x0.z; f[3] = x0.w;
    f[4] = x1.x; f[5] = x1.y; f[6] = x1.z; f[7] = x1.w;
}

// ============================================================
// GEMM body: C[M,N] = A @ W^T (+bias). 128x128, BK=16, packed tf32.
// ============================================================
__device__ __forceinline__ void gemm_body(const float* __restrict__ A,
                                          const float* __restrict__ W,
                                          const float* __restrict__ bias,
                                          float* __restrict__ C,
                                          int M, int N, int K, int m0, int n0) {
    __shared__ __align__(16) uint32_t sA[2][2 * (8 * 128 + 8)];
    __shared__ __align__(16) uint32_t sB[2][2 * (132 * 8 + 8)];
    const int tid = threadIdx.x;
    const int lrow = tid >> 1, oct = tid & 1, lk = oct * 8;
    const int lane = tid & 31, wid = tid >> 5;
    const int rb0 = (wid >> 1) * 2, nB = (wid & 1) * 64;
    const int gid = lane >> 2, tig = lane & 3;

    float acc[2][8][4];
#pragma unroll
    for (int i = 0; i < 2; i++)
#pragma unroll
        for (int j = 0; j < 8; j++)
#pragma unroll
            for (int c = 0; c < 4; c++) acc[i][j][c] = 0.f;

    const bool av = (m0 + lrow) < M, wv = (n0 + lrow) < N;
    const float* Ar = A + (size_t)(m0 + lrow) * K + lk;
    const float* Wr = W + (size_t)(n0 + lrow) * K + lk;
    float fA[8], fB[8];
    ld8(Ar, av, fA);
    ld8(Wr, wv, fB);
    storeA<8>(sA[0], oct, lrow, fA);
    storeB<132>(sB[0], oct, lrow, fB);
    __syncthreads();

    const int nk = K / 16;
    for (int kt = 0; kt < nk; kt++) {
        const int cur = kt & 1;
        const bool more = (kt + 1) < nk;
        if (more) {
            ld8(Ar + (kt + 1) * 16, av, fA);
            ld8(Wr + (kt + 1) * 16, wv, fB);
        }
#pragma unroll
        for (int o = 0; o < 2; o++) {
            uint4 a0 = loadA<8>(sA[cur], o, rb0, gid, tig);
            uint4 a1 = loadA<8>(sA[cur], o, rb0 + 1, gid, tig);
#pragma unroll
            for (int nt = 0; nt < 8; nt++) {
                uint2 bv = loadB<132>(sB[cur], o, tig, nB + nt * 8 + gid);
                mma_p(acc[0][nt], a0, bv);
                mma_p(acc[1][nt], a1, bv);
            }
        }
        if (more) {
            storeA<8>(sA[cur ^ 1], oct, lrow, fA);
            storeB<132>(sB[cur ^ 1], oct, lrow, fB);
            __syncthreads();
        }
    }

#pragma unroll
    for (int mt = 0; mt < 2; mt++) {
        int r = m0 + (rb0 + mt) * 16 + gid;
#pragma unroll
        for (int nt = 0; nt < 8; nt++) {
            int c = n0 + nB + nt * 8 + 2 * tig;
            float b0v = bias ? bias[c] : 0.f;
            float b1v = bias ? bias[c + 1] : 0.f;
            if (r < M)
                *(float2*)(C + (size_t)r * N + c) =
                    make_float2(acc[mt][nt][0] + b0v, acc[mt][nt][1] + b1v);
            if (r + 8 < M)
                *(float2*)(C + (size_t)(r + 8) * N + c) =
                    make_float2(acc[mt][nt][2] + b0v, acc[mt][nt][3] + b1v);
        }
    }
}

__global__ __launch_bounds__(256, 2) void gemm_tc_nt(
    const float* __restrict__ A, const float* __restrict__ W,
    const float* __restrict__ bias, float* __restrict__ C, int M, int N, int K) {
    gemm_body(A, W, bias, C, M, N, K, blockIdx.y * 128, blockIdx.x * 128);
}

// QKV + pos projections in one launch. grid (32, 32).
//   x in [0,24): sel 0..2 -> Q/K/V (M=4096), 8 n-blocks each
//   x in [24,32): pos (M=2047, uses y<16 only)
__global__ __launch_bounds__(256, 2) void gemm_qkvp(
    const float* __restrict__ A, const float* __restrict__ rpe,
    const float* __restrict__ Wq, const float* __restrict__ Wk, const float* __restrict__ Wv,
    const float* __restrict__ Wp,
    const float* __restrict__ bq, const float* __restrict__ bk, const float* __restrict__ bv,
    float* __restrict__ Cq, float* __restrict__ Ck, float* __restrict__ Cv,
    float* __restrict__ Cp) {
    const int sel = blockIdx.x >> 3;
    if (sel == 3) {
        if (blockIdx.y >= 16) return;
        gemm_body(rpe, Wp, nullptr, Cp, Lc, Dc, Dc, blockIdx.y * 128, (blockIdx.x & 7) * 128);
        return;
    }
    const float* W = (sel == 0) ? Wq : (sel == 1) ? Wk : Wv;
    const float* bias = (sel == 0) ? bq : (sel == 1) ? bk : bv;
    float* C = (sel == 0) ? Cq : (sel == 1) ? Ck : Cv;
    gemm_body(A, W, bias, C, Bc * Tc, Dc, Dc, blockIdx.y * 128, (blockIdx.x & 7) * 128);
}

// ============================================================
// FUSED attention per (bh, 32-row q tile) — software-pipelined strips
// smem (u32): Sb 32*1028 | Au 8*264 | Av 8*264 | Bf 2*8*552
// ============================================================
#define SB_STR 1028
#define AU_OFF (32 * SB_STR)
#define AV_OFF (AU_OFF + 8 * 264)
#define BF0_OFF (AV_OFF + 8 * 264)
#define BF1_OFF (BF0_OFF + 8 * 552)
#define FUSED_SMEM_BYTES ((BF1_OFF + 8 * 552) * 4)

__global__ __launch_bounds__(256, 1) void fused_attn(
    const float* __restrict__ Q, const float* __restrict__ K,
    const float* __restrict__ P, const float* __restrict__ V,
    const float* __restrict__ u, const float* __restrict__ vb,
    float* __restrict__ probs, float* __restrict__ ctx) {
    extern __shared__ __align__(16) uint32_t su[];
    float* Sb = (float*)su;
    uint32_t* Au = su + AU_OFF;
    uint32_t* Av = su + AV_OFF;
    uint32_t* Bf0 = su + BF0_OFF;

    const int t = threadIdx.x;
    const int bh = blockIdx.y, zb = bh >> 4, h = bh & 15;
    const int q0 = blockIdx.x * 32;
    const int lane = t & 31, w = t >> 5;
    const int mB = (w & 1) * 16, rbw = w & 1, nBf = (w >> 1) * 16;
    const int gid = lane >> 2, tig = lane & 3;

    // ---- stage q+u / q+v as packed A fragments (once) ----
    {
        int qr = t >> 3, o = t & 7;
        const float* qp = Q + ((size_t)(zb * Tc) + q0 + qr) * Dc + h * HSc + o * 8;
        const float* up = u + h * HSc + o * 8;
        const float* vp = vb + h * HSc + o * 8;
        float a[8], uu[8], fv[8];
        ld8(qp, true, a);
        ld8(up, true, uu);
        ld8(vp, true, fv);
        float fu2[8], fv2[8];
#pragma unroll
        for (int i = 0; i < 8; i++) { fu2[i] = a[i] + uu[i]; fv2[i] = a[i] + fv[i]; }
        storeA<2>(Au, o, qr, fu2);
        storeA<2>(Av, o, qr, fv2);
    }

    const int kr = t >> 2, qq = t & 3;
    float f0[8], f1[8];

    // ================= phase 1: ac = (q+u) K^T (pipelined) =================
    {
        const float* kp = K + ((size_t)(zb * Tc) + kr) * Dc + h * HSc + qq * 16;
        ld8(kp, true, f0);
        ld8(kp + 8, true, f1);
    }
    for (int j0 = 0; j0 < Tc; j0 += 64) {
        __syncthreads();                 // staging free (prev MMA / A-stage done)
        storeB<68>(Bf0, 2 * qq, kr, f0);
        storeB<68>(Bf0, 2 * qq + 1, kr, f1);
        __syncthreads();
        if (j0 + 64 < Tc) {              // prefetch next strip under this MMA
            const float* kp = K + ((size_t)(zb * Tc) + j0 + 64 + kr) * Dc + h * HSc + qq * 16;
            ld8(kp, true, f0);
            ld8(kp + 8, true, f1);
        }

        float acc[2][4] = {{0.f, 0.f, 0.f, 0.f}, {0.f, 0.f, 0.f, 0.f}};
#pragma unroll
        for (int o = 0; o < 8; o++) {
            uint4 a = loadA<2>(Au, o, rbw, gid, tig);
#pragma unroll
            for (int nt = 0; nt < 2; nt++)
                mma_p(acc[nt], a, loadB<68>(Bf0, o, tig, nBf + nt * 8 + gid));
        }
#pragma unroll
        for (int nt = 0; nt < 2; nt++) {
            int col = j0 + nBf + nt * 8 + 2 * tig;
            *(float2*)&Sb[(mB + gid) * SB_STR + col] = make_float2(acc[nt][0], acc[nt][1]);
            *(float2*)&Sb[(mB + gid + 8) * SB_STR + col] = make_float2(acc[nt][2], acc[nt][3]);
        }
    }

    // ================= phase 2: bd band, scatter-add (pipelined) =================
    const int lStart = (Tc - 1) - (q0 + 31);
    {
        int l = lStart + kr;
        if (l < Lc) {
            const float* pp = P + (size_t)l * Dc + h * HSc + qq * 16;
            ld8(pp, true, f0);
            ld8(pp + 8, true, f1);
        } else {
#pragma unroll
            for (int i = 0; i < 8; i++) { f0[i] = 0.f; f1[i] = 0.f; }
        }
    }
    for (int it = 0; it < 17; it++) {
        int lBase = lStart + it * 64;
        __syncthreads();
        storeB<68>(Bf0, 2 * qq, kr, f0);
        storeB<68>(Bf0, 2 * qq + 1, kr, f1);
        __syncthreads();
        if (it + 1 < 17) {
            int l = lBase + 64 + kr;
            if (l < Lc) {
                const float* pp = P + (size_t)l * Dc + h * HSc + qq * 16;
                ld8(pp, true, f0);
                ld8(pp + 8, true, f1);
            } else {
#pragma unroll
                for (int i = 0; i < 8; i++) { f0[i] = 0.f; f1[i] = 0.f; }
            }
        }

        float acc[2][4] = {{0.f, 0.f, 0.f, 0.f}, {0.f, 0.f, 0.f, 0.f}};
#pragma unroll
        for (int o = 0; o < 8; o++) {
            uint4 a = loadA<2>(Av, o, rbw, gid, tig);
#pragma unroll
            for (int nt = 0; nt < 2; nt++)
                mma_p(acc[nt], a, loadB<68>(Bf0, o, tig, nBf + nt * 8 + gid));
        }
#pragma unroll
        for (int nt = 0; nt < 2; nt++) {
            int lc = lBase + nBf + nt * 8 + 2 * tig;
            int m = mB + gid;
            int j = (q0 + m) + lc - (Tc - 1);
            if (j >= 0 && j < Tc) Sb[m * SB_STR + j] += acc[nt][0];
            if (j + 1 >= 0 && j + 1 < Tc) Sb[m * SB_STR + j + 1] += acc[nt][1];
            int j2 = j + 8;
            if (j2 >= 0 && j2 < Tc) Sb[(m + 8) * SB_STR + j2] += acc[nt][2];
            if (j2 + 1 >= 0 && j2 + 1 < Tc) Sb[(m + 8) * SB_STR + j2 + 1] += acc[nt][3];
        }
    }
    __syncthreads();

    // ================= phase 3: softmax (scale 0.125) =================
#pragma unroll
    for (int rr = 0; rr < 4; rr++) {
        float* row = Sb + (w * 4 + rr) * SB_STR;
        float mx = -3.4e38f;
        for (int c = lane; c < Tc; c += 32) mx = fmaxf(mx, row[c]);
#pragma unroll
        for (int o = 16; o; o >>= 1) mx = fmaxf(mx, __shfl_xor_sync(0xffffffffu, mx, o));
        float sum = 0.f;
        for (int c = lane; c < Tc; c += 32) {
            float e = expf(0.125f * (row[c] - mx));
            row[c] = e;
            sum += e;
        }
#pragma unroll
        for (int o = 16; o; o >>= 1) sum += __shfl_xor_sync(0xffffffffu, sum, o);
        float inv = 1.f / sum;
        for (int c = lane; c < Tc; c += 32) row[c] *= inv;
    }
    __syncthreads();

    // ---- write probs ----
    {
        float* pb = probs + ((size_t)bh << 20) + (size_t)q0 * Tc;
#pragma unroll 4
        for (int r = 0; r < 32; r++)
            *(float4*)(pb + (size_t)r * Tc + 4 * t) = *(float4*)&Sb[r * SB_STR + 4 * t];
    }

    // ================= phase 4: ctx = Sb @ V (pipelined) =================
    uint32_t* Vt = Bf0;  // 64*72 u32
    float acc2[2][4] = {{0.f, 0.f, 0.f, 0.f}, {0.f, 0.f, 0.f, 0.f}};
    float fv[16];
    {
        const float* vp = V + ((size_t)(zb * Tc) + kr) * Dc + h * HSc + qq * 16;
        ld8(vp, true, fv);
        ld8(vp + 8, true, fv + 8);
    }
    for (int kc = 0; kc < Tc; kc += 64) {
        __syncthreads();
        uint32_t* dst = Vt + kr * 72 + qq * 16;
        *(uint4*)(dst + 0)  = make_uint4(tf32_of(fv[0]),  tf32_of(fv[1]),  tf32_of(fv[2]),  tf32_of(fv[3]));
        *(uint4*)(dst + 4)  = make_uint4(tf32_of(fv[4]),  tf32_of(fv[5]),  tf32_of(fv[6]),  tf32_of(fv[7]));
        *(uint4*)(dst + 8)  = make_uint4(tf32_of(fv[8]),  tf32_of(fv[9]),  tf32_of(fv[10]), tf32_of(fv[11]));
        *(uint4*)(dst + 12) = make_uint4(tf32_of(fv[12]), tf32_of(fv[13]), tf32_of(fv[14]), tf32_of(fv[15]));
        __syncthreads();
        if (kc + 64 < Tc) {
            const float* vp = V + ((size_t)(zb * Tc) + kc + 64 + kr) * Dc + h * HSc + qq * 16;
            ld8(vp, true, fv);
            ld8(vp + 8, true, fv + 8);
        }

        const float* ar0 = Sb + (mB + gid) * SB_STR + kc;
        const float* ar8 = ar0 + 8 * SB_STR;
#pragma unroll
        for (int o = 0; o < 8; o++) {
            uint4 a;
            a.x = tf32_of(ar0[o * 8 + tig]);
            a.y = tf32_of(ar8[o * 8 + tig]);
            a.z = tf32_of(ar0[o * 8 + tig + 4]);
            a.w = tf32_of(ar8[o * 8 + tig + 4]);
#pragma unroll
            for (int nt = 0; nt < 2; nt++) {
                int c = nBf + nt * 8 + gid;
                uint2 b;
                b.x = Vt[(o * 8 + tig) * 72 + c];
                b.y = Vt[(o * 8 + tig + 4) * 72 + c];
                mma_p(acc2[nt], a, b);
            }
        }
    }
    {
        int r = q0 + mB + gid;
#pragma unroll
        for (int nt = 0; nt < 2; nt++) {
            int c = nBf + nt * 8 + 2 * tig;
            *(float2*)(ctx + ((size_t)(zb * Tc) + r) * Dc + h * HSc + c) =
                make_float2(acc2[nt][0], acc2[nt][1]);
            *(float2*)(ctx + ((size_t)(zb * Tc) + r + 8) * Dc + h * HSc + c) =
                make_float2(acc2[nt][2], acc2[nt][3]);
        }
    }
}

// ============================================================
extern "C" void kernel_launch(void* const* d_in, const int* in_sizes, int n_in,
                              void* d_out, int out_size) {
    const float* hs  = (const float*)d_in[0];
    const float* rpe = (const float*)d_in[1];
    const float* Wq  = (const float*)d_in[2];
    const float* bq  = (const float*)d_in[3];
    const float* Wk  = (const float*)d_in[4];
    const float* bk  = (const float*)d_in[5];
    const float* Wv  = (const float*)d_in[6];
    const float* bv  = (const float*)d_in[7];
    const float* Wo  = (const float*)d_in[8];
    const float* bo  = (const float*)d_in[9];
    const float* Wp  = (const float*)d_in[10];
    const float* pu  = (const float*)d_in[11];
    const float* pvb = (const float*)d_in[12];

    float* out = (float*)d_out;
    float* S   = out + (size_t)Bc * Tc * Dc;

    float *pq, *pk, *pv, *pp, *pctx;
    cudaGetSymbolAddress((void**)&pq,   g_q);
    cudaGetSymbolAddress((void**)&pk,   g_k);
    cudaGetSymbolAddress((void**)&pv,   g_v);
    cudaGetSymbolAddress((void**)&pp,   g_p);
    cudaGetSymbolAddress((void**)&pctx, g_ctx);

    cudaFuncSetAttribute(fused_attn, cudaFuncAttributeMaxDynamicSharedMemorySize,
                         FUSED_SMEM_BYTES);

    dim3 thr(256);
    gemm_qkvp<<<dim3(32, 32), thr>>>(hs, rpe, Wq, Wk, Wv, Wp, bq, bk, bv,
                                     pq, pk, pv, pp);

    fused_attn<<<dim3(Tc / 32, Bc * Hc), thr, FUSED_SMEM_BYTES>>>(
        pq, pk, pp, pv, pu, pvb, S, pctx);

    gemm_tc_nt<<<dim3(8, 32), thr>>>(pctx, Wo, bo, out, Bc * Tc, Dc, Dc);
}